// round 8
// baseline (speedup 1.0000x reference)
#include <cuda_runtime.h>
#include <cuda_bf16.h>
#include <cstdint>

// ---------------------------------------------------------------------------
// VectorQuantizer. tcgen05 bf16 6-term split GEMM + fused argmin (sm_103a),
// fp32 FFMA2 fallback (plain sm_103 pass). Persistent CTAs, bulk-async
// operand staging, dedicated producer/consumer warps, and DOUBLE-BUFFERED
// TMEM D (NT=128) so the argmin epilogue overlaps the next tile's MMAs.
// ---------------------------------------------------------------------------

#if defined(__CUDA_ARCH__) && (defined(__CUDA_ARCH_FEAT_SM103_ALL) || \
    defined(__CUDA_ARCH_FEAT_SM100_ALL) || defined(__CUDA_ARCH_FAMILY_SPECIFIC__))
#define HAS_TC 1
#else
#define HAS_TC 0
#endif

#define NROWS   8192
#define NCODES  16384
#define DIM     256
#define NZQ     2097152
#define OFF_LOSS NZQ
#define OFF_IDX  (NZQ + 1)

#define MT 256
#define NT 128
#define N_MT (NROWS / MT)     // 32
#define N_NT (NCODES / NT)    // 128
#define NTILES (N_MT * N_NT)  // 4096
#define GRID_MMA 148
#define NTHREADS 576          // 16 worker warps + consumer warp + producer warp
#define KC 64
#define STAGES_PER_TILE 24    // 4 kc x 6 terms
#define LOADS_PER_TILE 20

// ---- dynamic smem layout (bytes): A slots 2x32KB, B slots 3x16KB ----
#define SM_A(s)    ((s) * 32768)
#define SM_B(s)    (65536 + (s) * 16384)
#define SM_CD      114688
#define SM_CI      (SM_CD + 2048)
#define SM_TMEMPTR (SM_CI + 2048)
#define SM_MB      (SM_TMEMPTR + 8)
// mbar map: [0,16) mma-stage ring(2)  [16,48) tma ring(4)
//           [48,64) done ring(2)      [64,80) epi ring(2)
#define MB_STAGE(i) (SM_MB + (i) * 8)
#define MB_TMA(i)   (SM_MB + 16 + (i) * 8)
#define MB_DONE(i)  (SM_MB + 48 + (i) * 8)
#define MB_EPI(i)   (SM_MB + 64 + (i) * 8)
#define SMEM_DYN   (SM_MB + 96)

// idesc kind::f16: F32 acc(1<<4), A=BF16(1<<7), B=BF16(1<<10), N/8<<17, M/16<<24
#define IDESC 0x8200490u   // M=128, N=128

static __device__ __forceinline__ uint32_t smem_u32(const void* p) {
    return (uint32_t)__cvta_generic_to_shared(p);
}

// ---- device scratch ----
__device__ float g_zflat[NROWS * DIM];
__device__ float g_znorm[NROWS];
__device__ float g_enorm[NCODES];
// splits pre-swizzled: [block128][kc(4)][8192 bf16 = 16KB SW128 tile]
__device__ __nv_bfloat16 g_zs0[NROWS * DIM];
__device__ __nv_bfloat16 g_zs1[NROWS * DIM];
__device__ __nv_bfloat16 g_zs2[NROWS * DIM];
__device__ __nv_bfloat16 g_es0[NCODES * DIM];
__device__ __nv_bfloat16 g_es1[NCODES * DIM];
__device__ __nv_bfloat16 g_es2[NCODES * DIM];
__device__ float g_cand_d[N_NT * NROWS];
__device__ int   g_cand_i[N_NT * NROWS];
__device__ int   g_idx[NROWS];
__device__ float g_losspart[NROWS];

// tiled offset for (row n, col c) within a split array (element index)
static __device__ __forceinline__ size_t tiled_off(int n, int c) {
    int blk = n >> 7, r = n & 127, kc = c >> 6, cc = c & 63;
    return ((size_t)((blk << 2) + kc) << 13) + (size_t)r * 64 + (cc ^ ((r & 7) << 3));
}

// ---- packed f32x2 helpers (fallback path) ----
__device__ __forceinline__ unsigned long long pack2(float x, float y) {
    unsigned long long u;
    asm("mov.b64 %0, {%1, %2};" : "=l"(u)
        : "r"(__float_as_uint(x)), "r"(__float_as_uint(y)));
    return u;
}
__device__ __forceinline__ unsigned long long dup2(float x) {
    unsigned long long u;
    unsigned int r = __float_as_uint(x);
    asm("mov.b64 %0, {%1, %1};" : "=l"(u) : "r"(r));
    return u;
}
__device__ __forceinline__ void fma2(float2& d, unsigned long long a, unsigned long long b) {
    unsigned long long* dp = reinterpret_cast<unsigned long long*>(&d);
    asm("fma.rn.f32x2 %0, %1, %2, %0;" : "+l"(*dp) : "l"(a), "l"(b));
}

#if HAS_TC
#define MBAR_INIT(a, c) \
    asm volatile("mbarrier.init.shared.b64 [%0], %1;" :: "r"(a), "r"(c) : "memory")

#define MBAR_ARRIVE(a) \
    asm volatile("mbarrier.arrive.shared.b64 _, [%0];" :: "r"(a) : "memory")

#define MBAR_WAIT(a, par) do {                                               \
    asm volatile(                                                            \
        "{\n\t.reg .pred P1;\n\t"                                            \
        "WAIT_LOOP_%=:\n\t"                                                  \
        "mbarrier.try_wait.parity.acquire.cta.shared::cta.b64 P1, [%0], %1, 0x989680;\n\t" \
        "@P1 bra.uni WAIT_DONE_%=;\n\t"                                      \
        "bra.uni WAIT_LOOP_%=;\n\t"                                          \
        "WAIT_DONE_%=:\n\t}"                                                 \
        :: "r"(a), "r"(par) : "memory");                                     \
} while (0)

#define MBAR_EXPECT_TX(a, bytes) \
    asm volatile("mbarrier.arrive.expect_tx.shared.b64 _, [%0], %1;" \
                 :: "r"(a), "r"(bytes) : "memory")

#define BULK_G2S(dst, src, sz, mbar) \
    asm volatile("cp.async.bulk.shared::cta.global.mbarrier::complete_tx::bytes " \
                 "[%0], [%1], %2, [%3];" \
                 :: "r"(dst), "l"(src), "r"(sz), "r"(mbar) : "memory")

#define TC_ALLOC(smem_addr, ncols) \
    asm volatile("tcgen05.alloc.cta_group::1.sync.aligned.shared::cta.b32 [%0], %1;" \
                 :: "r"(smem_addr), "r"(ncols) : "memory")
#define TC_DEALLOC(tmem, ncols) \
    asm volatile("tcgen05.dealloc.cta_group::1.sync.aligned.b32 %0, %1;" :: "r"(tmem), "r"(ncols))
#define TC_RELINQ() \
    asm volatile("tcgen05.relinquish_alloc_permit.cta_group::1.sync.aligned;")
#define TC_COMMIT(mbar) \
    asm volatile("tcgen05.commit.cta_group::1.mbarrier::arrive::one.shared::cluster.b64 [%0];" \
                 :: "r"(mbar) : "memory")
#define TC_FENCE_AFTER()  asm volatile("tcgen05.fence::after_thread_sync;" ::: "memory")
#define TC_FENCE_BEFORE() asm volatile("tcgen05.fence::before_thread_sync;" ::: "memory")
#define TC_WAIT_LD()      asm volatile("tcgen05.wait::ld.sync.aligned;" ::: "memory")

static __device__ __forceinline__ void mma_f16_ss(
    uint32_t d_tmem, uint64_t a_desc, uint64_t b_desc, uint32_t idesc, bool acc)
{
    uint32_t en = acc ? 1u : 0u;
    asm volatile(
        "{\n\t.reg .pred p;\n\t"
        "setp.ne.u32 p, %4, 0;\n\t"
        "tcgen05.mma.cta_group::1.kind::f16 [%0], %1, %2, %3, {%5, %5, %5, %5}, p;\n\t"
        "}"
        :: "r"(d_tmem), "l"(a_desc), "l"(b_desc), "r"(idesc), "r"(en), "r"(0u)
        : "memory");
}

#define DESC_BASE ((2ULL << 61) | (1ULL << 46) | (64ULL << 32) | (1ULL << 16))
static __device__ __forceinline__ uint64_t mk_desc(uint32_t addr) {
    return DESC_BASE | ((uint64_t)(addr >> 4) & 0x3FFF);
}

#define LDTM_X32(r, a)                                                        \
    asm volatile("tcgen05.ld.sync.aligned.32x32b.x32.b32 "                    \
        "{%0,%1,%2,%3,%4,%5,%6,%7,%8,%9,%10,%11,%12,%13,%14,%15,"             \
        "%16,%17,%18,%19,%20,%21,%22,%23,%24,%25,%26,%27,%28,%29,%30,%31}, [%32];" \
        : "=r"((r)[0]),"=r"((r)[1]),"=r"((r)[2]),"=r"((r)[3]),                \
          "=r"((r)[4]),"=r"((r)[5]),"=r"((r)[6]),"=r"((r)[7]),                \
          "=r"((r)[8]),"=r"((r)[9]),"=r"((r)[10]),"=r"((r)[11]),              \
          "=r"((r)[12]),"=r"((r)[13]),"=r"((r)[14]),"=r"((r)[15]),            \
          "=r"((r)[16]),"=r"((r)[17]),"=r"((r)[18]),"=r"((r)[19]),            \
          "=r"((r)[20]),"=r"((r)[21]),"=r"((r)[22]),"=r"((r)[23]),            \
          "=r"((r)[24]),"=r"((r)[25]),"=r"((r)[26]),"=r"((r)[27]),            \
          "=r"((r)[28]),"=r"((r)[29]),"=r"((r)[30]),"=r"((r)[31])             \
        : "r"(a))
#endif // HAS_TC

// ---------------------------------------------------------------------------
// K0: transpose z (b,c,h,w) -> zflat[row][c] + bf16 3-split into tiled layout
// ---------------------------------------------------------------------------
__global__ void k_transpose(const float* __restrict__ z) {
    __shared__ float t[32][33];
    int b = blockIdx.z, h = blockIdx.y, c0 = blockIdx.x * 32;
    int tx = threadIdx.x, ty = threadIdx.y;
    t[ty][tx] = z[((size_t)(b * 256 + c0 + ty) * 32 + h) * 32 + tx];
    __syncthreads();
    int n = b * 1024 + h * 32 + ty;
    int c = c0 + tx;
    float x = t[tx][ty];
    g_zflat[(size_t)n * DIM + c] = x;
    __nv_bfloat16 h1 = __float2bfloat16(x);
    float r1 = __fsub_rn(x, __bfloat162float(h1));
    __nv_bfloat16 h2 = __float2bfloat16(r1);
    float r2 = __fsub_rn(r1, __bfloat162float(h2));
    size_t o = tiled_off(n, c);
    g_zs0[o] = h1; g_zs1[o] = h2; g_zs2[o] = __float2bfloat16(r2);
}

// ---------------------------------------------------------------------------
// K1: row norms (reference elementwise square + k-ascending sum rounding)
// ---------------------------------------------------------------------------
__global__ void k_norms(const float* __restrict__ emb) {
    int i = blockIdx.x * blockDim.x + threadIdx.x;
    if (i < NROWS) {
        const float4* p = reinterpret_cast<const float4*>(g_zflat + (size_t)i * DIM);
        float s = 0.f;
        #pragma unroll 8
        for (int c = 0; c < DIM / 4; ++c) {
            float4 v = p[c];
            s = __fadd_rn(s, __fmul_rn(v.x, v.x));
            s = __fadd_rn(s, __fmul_rn(v.y, v.y));
            s = __fadd_rn(s, __fmul_rn(v.z, v.z));
            s = __fadd_rn(s, __fmul_rn(v.w, v.w));
        }
        g_znorm[i] = s;
    } else if (i < NROWS + NCODES) {
        int k = i - NROWS;
        const float4* p = reinterpret_cast<const float4*>(emb + (size_t)k * DIM);
        float s = 0.f;
        #pragma unroll 8
        for (int c = 0; c < DIM / 4; ++c) {
            float4 v = p[c];
            s = __fadd_rn(s, __fmul_rn(v.x, v.x));
            s = __fadd_rn(s, __fmul_rn(v.y, v.y));
            s = __fadd_rn(s, __fmul_rn(v.z, v.z));
            s = __fadd_rn(s, __fmul_rn(v.w, v.w));
        }
        g_enorm[k] = s;
    }
}

// ---------------------------------------------------------------------------
// K2: embedding bf16 3-way split into tiled layout
// ---------------------------------------------------------------------------
__global__ void k_split_e(const float* __restrict__ emb) {
    int i = blockIdx.x * blockDim.x + threadIdx.x;
    if (i >= NCODES * DIM) return;
    int k = i >> 8, c = i & 255;
    float x = emb[i];
    __nv_bfloat16 h1 = __float2bfloat16(x);
    float r1 = __fsub_rn(x, __bfloat162float(h1));
    __nv_bfloat16 h2 = __float2bfloat16(r1);
    float r2 = __fsub_rn(r1, __bfloat162float(h2));
    size_t o = tiled_off(k, c);
    g_es0[o] = h1; g_es1[o] = h2; g_es2[o] = __float2bfloat16(r2);
}

// ---------------------------------------------------------------------------
// K3: persistent GEMM + fused argmin. grid=148, 576 threads.
// Tile 256(M, 2 subtiles) x 128(N). D double-buffered in TMEM (2 x 256 cols).
// warps 0-15: epilogue workers   warp 16 (tid 512): MMA consumer
// warp 17 (tid 544): bulk-copy producer.
// Reuse schedule per kc (A 2 slots X/Y, B 3 slots), hazard distance >= 2:
//   j:      0      1      2      3      4      5
//   term:  z1e2   z1e3   z1e1   z2e2   z2e1   z3e1
//   aslot:  X      X      X      Y      Y      X     (X = kc&1)
//   bslot:  0      1      2      0      2      2
//   load:  z1,e2   e3     e1     z2     --     z3
// Rings: tma(4) producer->consumer; mma-stage(2) commits guard smem slot
// reuse (producer waits gs-2); done(2) consumer->workers per tile; epi(2,
// count 512) workers->consumer frees the D buffer for tile ti+2.
// ---------------------------------------------------------------------------
__global__ __launch_bounds__(NTHREADS, 1) void k_mma(const float* __restrict__ emb) {
    extern __shared__ char smem[];
    const int tid = threadIdx.x;

#if HAS_TC
    const uint32_t sbase = smem_u32(smem);
    const int wid = tid >> 5;
    const int lane = tid & 31;

    if (wid == 0) TC_ALLOC(sbase + SM_TMEMPTR, 512);
    if (tid == 0) {
        MBAR_INIT(MB_STAGE(0) + sbase, 1);
        MBAR_INIT(MB_STAGE(1) + sbase, 1);
        #pragma unroll
        for (int q = 0; q < 4; ++q) MBAR_INIT(MB_TMA(q) + sbase, 1);
        MBAR_INIT(MB_DONE(0) + sbase, 1);
        MBAR_INIT(MB_DONE(1) + sbase, 1);
        MBAR_INIT(MB_EPI(0) + sbase, 512);
        MBAR_INIT(MB_EPI(1) + sbase, 512);
    }
    __syncthreads();
    uint32_t tmem;
    asm volatile("ld.shared.b32 %0, [%1];" : "=r"(tmem) : "r"(sbase + SM_TMEMPTR));

    const int tab_as[6] = {0, 0, 0, 1, 1, 0};
    const int tab_bs[6] = {0, 1, 2, 0, 2, 2};

    if (tid == 512) {
        // ================= consumer: issue MMAs =================
        int ti = 0;
        for (int tile = blockIdx.x; tile < NTILES; tile += GRID_MMA, ++ti) {
            if (ti >= 2) {   // D buffer (ti&1) free after epilogue of ti-2
                MBAR_WAIT(MB_EPI(ti & 1) + sbase, ((ti - 2) >> 1) & 1);
            }
            TC_FENCE_AFTER();
            const uint32_t dbase = tmem + (ti & 1) * 256;
            int gs = ti * STAGES_PER_TILE;
            int ln = ti * LOADS_PER_TILE;
            for (int s = 0; s < STAGES_PER_TILE; ++s, ++gs) {
                const int kc = s / 6;
                const int j  = s - kc * 6;
                if (j != 4) {
                    MBAR_WAIT(MB_TMA(ln & 3) + sbase, (ln >> 2) & 1);
                    ++ln;
                }
                const int a_slot = tab_as[j] ^ (kc & 1);
                const int b_slot = tab_bs[j];
                uint64_t bd = mk_desc(sbase + SM_B(b_slot));
                #pragma unroll
                for (int sb2 = 0; sb2 < 2; ++sb2) {
                    uint64_t ad = mk_desc(sbase + SM_A(a_slot) + sb2 * 16384);
                    #pragma unroll
                    for (int k = 0; k < 4; ++k)
                        mma_f16_ss(dbase + sb2 * 128, ad + k * 2, bd + k * 2,
                                   IDESC, (s > 0) || (k > 0));
                }
                TC_COMMIT(MB_STAGE(gs & 1) + sbase);
            }
            // drain this tile's MMAs, then signal workers
            int w = gs - 1;
            MBAR_WAIT(MB_STAGE(w & 1) + sbase, (w >> 1) & 1);
            MBAR_ARRIVE(MB_DONE(ti & 1) + sbase);
        }
    } else if (tid == 544) {
        // ================= producer: bulk copies =================
        int ti = 0;
        for (int tile = blockIdx.x; tile < NTILES; tile += GRID_MMA, ++ti) {
            const int mblk = (tile & (N_MT - 1)) * 2;   // 2 z-blocks of 128
            const int nblk = tile >> 5;                 // 1 e-block of 128
            int gs = ti * STAGES_PER_TILE;
            int ln = ti * LOADS_PER_TILE;
            for (int s = 0; s < STAGES_PER_TILE; ++s, ++gs) {
                const int kc = s / 6;
                const int j  = s - kc * 6;
                if (j == 4) continue;
                if (gs >= 2) {   // slot-reuse hazard: wait stage gs-2's MMAs
                    int w = gs - 2;
                    MBAR_WAIT(MB_STAGE(w & 1) + sbase, (w >> 1) & 1);
                }
                const uint32_t mb = MB_TMA(ln & 3) + sbase;
                const uint32_t bytes = (j == 0) ? 49152u
                                     : (j == 1 || j == 2) ? 16384u : 32768u;
                MBAR_EXPECT_TX(mb, bytes);
                const int a_slot = tab_as[j] ^ (kc & 1);
                const int b_slot = tab_bs[j];
                if (j == 0 || j == 3 || j == 5) {   // A load: z1 / z2 / z3
                    const char* src = (j == 0) ? (const char*)g_zs0
                                    : (j == 3) ? (const char*)g_zs1
                                               : (const char*)g_zs2;
                    #pragma unroll
                    for (int sb2 = 0; sb2 < 2; ++sb2)
                        BULK_G2S(sbase + SM_A(a_slot) + sb2 * 16384,
                                 src + ((size_t)((mblk + sb2) * 4 + kc) << 14),
                                 16384u, mb);
                }
                if (j == 0 || j == 1 || j == 2) {   // B load: e2 / e3 / e1
                    const char* src = (j == 0) ? (const char*)g_es1
                                    : (j == 1) ? (const char*)g_es2
                                               : (const char*)g_es0;
                    BULK_G2S(sbase + SM_B(b_slot),
                             src + ((size_t)(nblk * 4 + kc) << 14),
                             16384u, mb);
                }
                ++ln;
            }
        }
    } else if (wid < 16) {
        // ================= workers: epilogue =================
        float* cd = reinterpret_cast<float*>(smem + SM_CD);
        int*   ci = reinterpret_cast<int*>(smem + SM_CI);
        const int sub = (wid >> 2) & 1;       // subtile (row block of 128)
        const int h   = wid >> 3;             // column half (64 cols)
        const int rl  = (wid & 3) * 32 + lane; // TMEM lane = row in subtile

        int ti = 0;
        for (int tile = blockIdx.x; tile < NTILES; tile += GRID_MMA, ++ti) {
            const int m0 = (tile & (N_MT - 1)) * MT;
            const int n_tile = tile >> 5;
            const int n0 = n_tile * NT;

            MBAR_WAIT(MB_DONE(ti & 1) + sbase, (ti >> 1) & 1);
            TC_FENCE_AFTER();
            const uint32_t dbase = tmem + (ti & 1) * 256;

            const float zn = g_znorm[m0 + sub * 128 + rl];
            float bd2 = 3.4e38f;
            int   bi2 = 0;
            #pragma unroll
            for (int jj = 0; jj < 2; ++jj) {
                uint32_t regs[32];
                LDTM_X32(regs, dbase + sub * 128 + h * 64 + jj * 32);
                TC_WAIT_LD();
                #pragma unroll
                for (int c = 0; c < 32; ++c) {
                    int code = n0 + h * 64 + jj * 32 + c;
                    float dot = __uint_as_float(regs[c]);
                    float d = __fmaf_rn(-2.f, dot,
                                        __fadd_rn(zn, __ldg(&g_enorm[code])));
                    if (d < bd2) { bd2 = d; bi2 = code; }
                }
            }
            TC_FENCE_BEFORE();
            MBAR_ARRIVE(MB_EPI(ti & 1) + sbase);   // D buffer free (my LDTMs done)

            cd[(sub * 128 + rl) * 2 + h] = bd2;
            ci[(sub * 128 + rl) * 2 + h] = bi2;
            asm volatile("bar.sync 1, 512;" ::: "memory");

            if (tid < 256) {
                float d0 = cd[tid * 2], d1 = cd[tid * 2 + 1];
                int   i0 = ci[tid * 2], i1 = ci[tid * 2 + 1];
                if (d1 < d0) { d0 = d1; i0 = i1; }  // half0 first => first-index
                g_cand_d[n_tile * NROWS + m0 + tid] = d0;
                g_cand_i[n_tile * NROWS + m0 + tid] = i0;
            }
            asm volatile("bar.sync 1, 512;" ::: "memory");
        }
    }

    __syncthreads();
    if (wid == 0) {
        TC_RELINQ();
        TC_DEALLOC(tmem, 512);
    }

#else  // ---------------- fallback: fp32 FFMA2 GEMM-argmin ------------------
    float (*As)[260] = reinterpret_cast<float(*)[260]>(smem);
    float (*Bs)[132] = reinterpret_cast<float(*)[132]>(smem + 33280);

    const int tx = tid & 15;
    const int ty = tid >> 4;
    const int lk = tid & 31;
    const int lm = tid >> 5;
    const bool act = tid < 512;

    for (int tile = blockIdx.x; tile < NTILES; tile += GRID_MMA) {
        const int m0 = (tile & (N_MT - 1)) * MT;
        const int n_tile = tile >> 5;
        const int n0 = n_tile * NT;

        float zn8[8];
        float bestd[8];
        int   besti[8];
        if (act) {
            #pragma unroll
            for (int r = 0; r < 8; ++r) {
                zn8[r] = g_znorm[m0 + ty * 8 + r];
                bestd[r] = 3.4e38f; besti[r] = 0;
            }
        }

        float2 acc[8][4];
        if (act) {
            #pragma unroll
            for (int r = 0; r < 8; ++r)
                #pragma unroll
                for (int j = 0; j < 4; ++j) acc[r][j] = make_float2(0.f, 0.f);
        }

        for (int k0 = 0; k0 < DIM; k0 += 32) {
            __syncthreads();
            if (act) {
                #pragma unroll
                for (int j = 0; j < 16; ++j) {
                    int row = lm + j * 16;
                    As[lk][row] = g_zflat[(size_t)(m0 + row) * DIM + k0 + lk];
                }
                #pragma unroll
                for (int j = 0; j < 8; ++j) {
                    int row = lm + j * 16;
                    if (row < NT)
                        Bs[lk][row] = emb[(size_t)(n0 + row) * DIM + k0 + lk];
                }
            }
            __syncthreads();
            if (act) {
                #pragma unroll
                for (int k = 0; k < 32; ++k) {
                    float4 a0 = *reinterpret_cast<const float4*>(&As[k][ty * 8]);
                    float4 a1 = *reinterpret_cast<const float4*>(&As[k][ty * 8 + 4]);
                    float4 b0 = *reinterpret_cast<const float4*>(&Bs[k][(tx & 7) * 8]);
                    float4 b1 = *reinterpret_cast<const float4*>(&Bs[k][(tx & 7) * 8 + 4]);
                    unsigned long long bp0 = pack2(b0.x, b0.y);
                    unsigned long long bp1 = pack2(b0.z, b0.w);
                    unsigned long long bp2 = pack2(b1.x, b1.y);
                    unsigned long long bp3 = pack2(b1.z, b1.w);
                    float av[8] = {a0.x, a0.y, a0.z, a0.w, a1.x, a1.y, a1.z, a1.w};
                    if (tx < 8) {
                        #pragma unroll
                        for (int r = 0; r < 8; ++r) {
                            unsigned long long ap = dup2(av[r]);
                            fma2(acc[r][0], ap, bp0);
                            fma2(acc[r][1], ap, bp1);
                            fma2(acc[r][2], ap, bp2);
                            fma2(acc[r][3], ap, bp3);
                        }
                    }
                }
            }
        }

        if (act && tx < 8) {
            #pragma unroll
            for (int j = 0; j < 8; ++j) {
                int code = n0 + (tx & 7) * 8 + j;
                float en = __ldg(&g_enorm[code]);
                #pragma unroll
                for (int r = 0; r < 8; ++r) {
                    float dot = (j & 1) ? acc[r][j >> 1].y : acc[r][j >> 1].x;
                    float d = __fmaf_rn(-2.f, dot, __fadd_rn(zn8[r], en));
                    if (d < bestd[r]) { bestd[r] = d; besti[r] = code; }
                }
            }
        }

        if (act) {
            #pragma unroll
            for (int r = 0; r < 8; ++r) {
                float bd = (tx < 8) ? bestd[r] : 3.4e38f;
                int   bi = (tx < 8) ? besti[r] : 0x7fffffff;
                #pragma unroll
                for (int off = 8; off > 0; off >>= 1) {
                    float od = __shfl_down_sync(0xffffffffu, bd, off, 16);
                    int   oi = __shfl_down_sync(0xffffffffu, bi, off, 16);
                    if (od < bd || (od == bd && oi < bi)) { bd = od; bi = oi; }
                }
                if (tx == 0) {
                    int row = m0 + ty * 8 + r;
                    g_cand_d[n_tile * NROWS + row] = bd;
                    g_cand_i[n_tile * NROWS + row] = bi;
                }
            }
        }
        __syncthreads();
    }
#endif
}

// ---------------------------------------------------------------------------
// K4: merge 128 n-chunks per row (ascending => first-index tie-break)
// ---------------------------------------------------------------------------
__global__ void k_merge(float* __restrict__ out, int out_size) {
    int i = blockIdx.x * blockDim.x + threadIdx.x;
    if (i >= NROWS) return;
    float d0 = g_cand_d[i];
    int   i0 = g_cand_i[i];
    for (int s = 1; s < N_NT; ++s) {
        float d1 = g_cand_d[s * NROWS + i];
        int   i1 = g_cand_i[s * NROWS + i];
        if (d1 < d0) { d0 = d1; i0 = i1; }
    }
    g_idx[i] = i0;
    if (out_size > OFF_IDX + i) out[OFF_IDX + i] = (float)i0;
}

// ---------------------------------------------------------------------------
// K5: gather + straight-through + transpose back + loss partials
// ---------------------------------------------------------------------------
__global__ void k_gather(const float* __restrict__ emb, float* __restrict__ out) {
    __shared__ float red[256];
    int n = blockIdx.x, c = threadIdx.x;
    int b = n >> 10, hw = n & 1023;
    int code = g_idx[n];
    float zf = g_zflat[(size_t)n * DIM + c];
    float zq = emb[(size_t)code * DIM + c];
    float diff = __fsub_rn(zq, zf);
    float st = __fadd_rn(zf, diff);
    out[(size_t)(b * 256 + c) * 1024 + hw] = st;
    red[c] = __fmul_rn(diff, diff);
    __syncthreads();
    #pragma unroll
    for (int s = 128; s > 0; s >>= 1) {
        if (c < s) red[c] = __fadd_rn(red[c], red[c + s]);
        __syncthreads();
    }
    if (c == 0) g_losspart[n] = red[0];
}

__global__ void k_loss(float* __restrict__ out, int out_size) {
    __shared__ float red[256];
    int t = threadIdx.x;
    float s = 0.f;
    for (int i = t; i < NROWS; i += 256) s = __fadd_rn(s, g_losspart[i]);
    red[t] = s;
    __syncthreads();
    #pragma unroll
    for (int k = 128; k > 0; k >>= 1) {
        if (t < k) red[t] = __fadd_rn(red[t], red[t + k]);
        __syncthreads();
    }
    if (t == 0 && out_size > OFF_LOSS)
        out[OFF_LOSS] = 1.25f * red[0] / 2097152.0f;
}

// ---------------------------------------------------------------------------
extern "C" void kernel_launch(void* const* d_in, const int* in_sizes, int n_in,
                              void* d_out, int out_size) {
    const float* z   = (const float*)d_in[0];
    const float* emb = (const float*)d_in[1];
    if (n_in >= 2 && in_sizes[0] == NCODES * DIM && in_sizes[1] == NROWS * DIM) {
        const float* t = z; z = emb; emb = t;
    }
    float* out = (float*)d_out;

    cudaFuncSetAttribute(k_mma, cudaFuncAttributeMaxDynamicSharedMemorySize, SMEM_DYN);

    k_transpose<<<dim3(8, 32, 8), dim3(32, 32)>>>(z);
    k_norms<<<(NROWS + NCODES + 255) / 256, 256>>>(emb);
    k_split_e<<<(NCODES * DIM + 255) / 256, 256>>>(emb);
    k_mma<<<GRID_MMA, NTHREADS, SMEM_DYN>>>(emb);
    k_merge<<<NROWS / 256, 256>>>(out, out_size);
    k_gather<<<NROWS, 256>>>(emb, out);
    k_loss<<<1, 256>>>(out, out_size);
}

// round 9
// speedup vs baseline: 1.3114x; 1.3114x over previous
#include <cuda_runtime.h>
#include <cuda_bf16.h>
#include <cstdint>

// ---------------------------------------------------------------------------
// VectorQuantizer. tcgen05 bf16 6-term split GEMM + fused argmin (sm_103a),
// fp32 FFMA2 fallback (plain sm_103 pass). R6 tile shape (256x256, proven
// 320us) + dedicated producer/consumer/worker warps so next-tile loads
// overlap the argmin epilogue. Single TMEM D buffer (512 cols).
// ---------------------------------------------------------------------------

#if defined(__CUDA_ARCH__) && (defined(__CUDA_ARCH_FEAT_SM103_ALL) || \
    defined(__CUDA_ARCH_FEAT_SM100_ALL) || defined(__CUDA_ARCH_FAMILY_SPECIFIC__))
#define HAS_TC 1
#else
#define HAS_TC 0
#endif

#define NROWS   8192
#define NCODES  16384
#define DIM     256
#define NZQ     2097152
#define OFF_LOSS NZQ
#define OFF_IDX  (NZQ + 1)

#define MT 256
#define NT 256
#define N_MT (NROWS / MT)     // 32
#define N_NT (NCODES / NT)    // 64
#define NTILES (N_MT * N_NT)  // 2048
#define GRID_MMA 148
#define NTHREADS 576          // 16 worker warps + consumer + producer
#define KC 64
#define STAGES_PER_TILE 24    // 4 kc x 6 terms
#define LOADS_PER_TILE 20

// ---- dynamic smem layout (bytes): A slots 2x32KB, B slots 3x32KB ----
#define SM_A(s)    ((s) * 32768)
#define SM_B(s)    (65536 + (s) * 32768)
#define SM_CD      163840
#define SM_CI      (SM_CD + 2048)
#define SM_TMEMPTR (SM_CI + 2048)
#define SM_MB      (SM_TMEMPTR + 8)
// mbar map: [0,16) mma-stage ring(2)  [16,48) tma ring(4)  [48,56) done  [56,64) epi
#define MB_STAGE(i) (SM_MB + (i) * 8)
#define MB_TMA(i)   (SM_MB + 16 + (i) * 8)
#define MB_DONE     (SM_MB + 48)
#define MB_EPI      (SM_MB + 56)
#define SMEM_DYN   (SM_MB + 80)

// idesc kind::f16: F32 acc(1<<4), A=BF16(1<<7), B=BF16(1<<10), N/8<<17, M/16<<24
#define IDESC 0x8400490u   // M=128, N=256

static __device__ __forceinline__ uint32_t smem_u32(const void* p) {
    return (uint32_t)__cvta_generic_to_shared(p);
}

// ---- device scratch ----
__device__ float g_zflat[NROWS * DIM];
__device__ float g_znorm[NROWS];
__device__ float g_enorm[NCODES];
// splits pre-swizzled: [block128][kc(4)][8192 bf16 = 16KB SW128 tile]
__device__ __nv_bfloat16 g_zs0[NROWS * DIM];
__device__ __nv_bfloat16 g_zs1[NROWS * DIM];
__device__ __nv_bfloat16 g_zs2[NROWS * DIM];
__device__ __nv_bfloat16 g_es0[NCODES * DIM];
__device__ __nv_bfloat16 g_es1[NCODES * DIM];
__device__ __nv_bfloat16 g_es2[NCODES * DIM];
__device__ float g_cand_d[N_NT * NROWS];
__device__ int   g_cand_i[N_NT * NROWS];
__device__ int   g_idx[NROWS];
__device__ float g_losspart[NROWS];

// tiled offset for (row n, col c) within a split array (element index)
static __device__ __forceinline__ size_t tiled_off(int n, int c) {
    int blk = n >> 7, r = n & 127, kc = c >> 6, cc = c & 63;
    return ((size_t)((blk << 2) + kc) << 13) + (size_t)r * 64 + (cc ^ ((r & 7) << 3));
}

// ---- packed f32x2 helpers (fallback path) ----
__device__ __forceinline__ unsigned long long pack2(float x, float y) {
    unsigned long long u;
    asm("mov.b64 %0, {%1, %2};" : "=l"(u)
        : "r"(__float_as_uint(x)), "r"(__float_as_uint(y)));
    return u;
}
__device__ __forceinline__ unsigned long long dup2(float x) {
    unsigned long long u;
    unsigned int r = __float_as_uint(x);
    asm("mov.b64 %0, {%1, %1};" : "=l"(u) : "r"(r));
    return u;
}
__device__ __forceinline__ void fma2(float2& d, unsigned long long a, unsigned long long b) {
    unsigned long long* dp = reinterpret_cast<unsigned long long*>(&d);
    asm("fma.rn.f32x2 %0, %1, %2, %0;" : "+l"(*dp) : "l"(a), "l"(b));
}

#if HAS_TC
#define MBAR_INIT(a, c) \
    asm volatile("mbarrier.init.shared.b64 [%0], %1;" :: "r"(a), "r"(c) : "memory")

#define MBAR_ARRIVE(a) \
    asm volatile("mbarrier.arrive.shared.b64 _, [%0];" :: "r"(a) : "memory")

#define MBAR_WAIT(a, par) do {                                               \
    asm volatile(                                                            \
        "{\n\t.reg .pred P1;\n\t"                                            \
        "WAIT_LOOP_%=:\n\t"                                                  \
        "mbarrier.try_wait.parity.acquire.cta.shared::cta.b64 P1, [%0], %1, 0x989680;\n\t" \
        "@P1 bra.uni WAIT_DONE_%=;\n\t"                                      \
        "bra.uni WAIT_LOOP_%=;\n\t"                                          \
        "WAIT_DONE_%=:\n\t}"                                                 \
        :: "r"(a), "r"(par) : "memory");                                     \
} while (0)

#define MBAR_EXPECT_TX(a, bytes) \
    asm volatile("mbarrier.arrive.expect_tx.shared.b64 _, [%0], %1;" \
                 :: "r"(a), "r"(bytes) : "memory")

#define BULK_G2S(dst, src, sz, mbar) \
    asm volatile("cp.async.bulk.shared::cta.global.mbarrier::complete_tx::bytes " \
                 "[%0], [%1], %2, [%3];" \
                 :: "r"(dst), "l"(src), "r"(sz), "r"(mbar) : "memory")

#define TC_ALLOC(smem_addr, ncols) \
    asm volatile("tcgen05.alloc.cta_group::1.sync.aligned.shared::cta.b32 [%0], %1;" \
                 :: "r"(smem_addr), "r"(ncols) : "memory")
#define TC_DEALLOC(tmem, ncols) \
    asm volatile("tcgen05.dealloc.cta_group::1.sync.aligned.b32 %0, %1;" :: "r"(tmem), "r"(ncols))
#define TC_RELINQ() \
    asm volatile("tcgen05.relinquish_alloc_permit.cta_group::1.sync.aligned;")
#define TC_COMMIT(mbar) \
    asm volatile("tcgen05.commit.cta_group::1.mbarrier::arrive::one.shared::cluster.b64 [%0];" \
                 :: "r"(mbar) : "memory")
#define TC_FENCE_AFTER()  asm volatile("tcgen05.fence::after_thread_sync;" ::: "memory")
#define TC_FENCE_BEFORE() asm volatile("tcgen05.fence::before_thread_sync;" ::: "memory")
#define TC_WAIT_LD()      asm volatile("tcgen05.wait::ld.sync.aligned;" ::: "memory")

static __device__ __forceinline__ void mma_f16_ss(
    uint32_t d_tmem, uint64_t a_desc, uint64_t b_desc, uint32_t idesc, bool acc)
{
    uint32_t en = acc ? 1u : 0u;
    asm volatile(
        "{\n\t.reg .pred p;\n\t"
        "setp.ne.u32 p, %4, 0;\n\t"
        "tcgen05.mma.cta_group::1.kind::f16 [%0], %1, %2, %3, {%5, %5, %5, %5}, p;\n\t"
        "}"
        :: "r"(d_tmem), "l"(a_desc), "l"(b_desc), "r"(idesc), "r"(en), "r"(0u)
        : "memory");
}

#define DESC_BASE ((2ULL << 61) | (1ULL << 46) | (64ULL << 32) | (1ULL << 16))
static __device__ __forceinline__ uint64_t mk_desc(uint32_t addr) {
    return DESC_BASE | ((uint64_t)(addr >> 4) & 0x3FFF);
}

#define LDTM_X32(r, a)                                                        \
    asm volatile("tcgen05.ld.sync.aligned.32x32b.x32.b32 "                    \
        "{%0,%1,%2,%3,%4,%5,%6,%7,%8,%9,%10,%11,%12,%13,%14,%15,"             \
        "%16,%17,%18,%19,%20,%21,%22,%23,%24,%25,%26,%27,%28,%29,%30,%31}, [%32];" \
        : "=r"((r)[0]),"=r"((r)[1]),"=r"((r)[2]),"=r"((r)[3]),                \
          "=r"((r)[4]),"=r"((r)[5]),"=r"((r)[6]),"=r"((r)[7]),                \
          "=r"((r)[8]),"=r"((r)[9]),"=r"((r)[10]),"=r"((r)[11]),              \
          "=r"((r)[12]),"=r"((r)[13]),"=r"((r)[14]),"=r"((r)[15]),            \
          "=r"((r)[16]),"=r"((r)[17]),"=r"((r)[18]),"=r"((r)[19]),            \
          "=r"((r)[20]),"=r"((r)[21]),"=r"((r)[22]),"=r"((r)[23]),            \
          "=r"((r)[24]),"=r"((r)[25]),"=r"((r)[26]),"=r"((r)[27]),            \
          "=r"((r)[28]),"=r"((r)[29]),"=r"((r)[30]),"=r"((r)[31])             \
        : "r"(a))
#endif // HAS_TC

// ---------------------------------------------------------------------------
// K0: transpose z (b,c,h,w) -> zflat[row][c] + bf16 3-split into tiled layout
// ---------------------------------------------------------------------------
__global__ void k_transpose(const float* __restrict__ z) {
    __shared__ float t[32][33];
    int b = blockIdx.z, h = blockIdx.y, c0 = blockIdx.x * 32;
    int tx = threadIdx.x, ty = threadIdx.y;
    t[ty][tx] = z[((size_t)(b * 256 + c0 + ty) * 32 + h) * 32 + tx];
    __syncthreads();
    int n = b * 1024 + h * 32 + ty;
    int c = c0 + tx;
    float x = t[tx][ty];
    g_zflat[(size_t)n * DIM + c] = x;
    __nv_bfloat16 h1 = __float2bfloat16(x);
    float r1 = __fsub_rn(x, __bfloat162float(h1));
    __nv_bfloat16 h2 = __float2bfloat16(r1);
    float r2 = __fsub_rn(r1, __bfloat162float(h2));
    size_t o = tiled_off(n, c);
    g_zs0[o] = h1; g_zs1[o] = h2; g_zs2[o] = __float2bfloat16(r2);
}

// ---------------------------------------------------------------------------
// K1: row norms (reference elementwise square + k-ascending sum rounding)
// ---------------------------------------------------------------------------
__global__ void k_norms(const float* __restrict__ emb) {
    int i = blockIdx.x * blockDim.x + threadIdx.x;
    if (i < NROWS) {
        const float4* p = reinterpret_cast<const float4*>(g_zflat + (size_t)i * DIM);
        float s = 0.f;
        #pragma unroll 8
        for (int c = 0; c < DIM / 4; ++c) {
            float4 v = p[c];
            s = __fadd_rn(s, __fmul_rn(v.x, v.x));
            s = __fadd_rn(s, __fmul_rn(v.y, v.y));
            s = __fadd_rn(s, __fmul_rn(v.z, v.z));
            s = __fadd_rn(s, __fmul_rn(v.w, v.w));
        }
        g_znorm[i] = s;
    } else if (i < NROWS + NCODES) {
        int k = i - NROWS;
        const float4* p = reinterpret_cast<const float4*>(emb + (size_t)k * DIM);
        float s = 0.f;
        #pragma unroll 8
        for (int c = 0; c < DIM / 4; ++c) {
            float4 v = p[c];
            s = __fadd_rn(s, __fmul_rn(v.x, v.x));
            s = __fadd_rn(s, __fmul_rn(v.y, v.y));
            s = __fadd_rn(s, __fmul_rn(v.z, v.z));
            s = __fadd_rn(s, __fmul_rn(v.w, v.w));
        }
        g_enorm[k] = s;
    }
}

// ---------------------------------------------------------------------------
// K2: embedding bf16 3-way split, vectorized 8 elements/thread.
// 8 consecutive (8-aligned) cols stay contiguous in the tiled layout: the
// swizzle xors the 8-group index only.
// ---------------------------------------------------------------------------
__global__ void k_split_e(const float* __restrict__ emb) {
    int i = blockIdx.x * blockDim.x + threadIdx.x;     // i indexes groups of 8
    if (i >= NCODES * DIM / 8) return;
    int k = i >> 5, c8 = (i & 31) * 8;
    const float4* src = reinterpret_cast<const float4*>(emb + (size_t)k * DIM + c8);
    float4 v0 = src[0], v1 = src[1];
    float xs[8] = {v0.x, v0.y, v0.z, v0.w, v1.x, v1.y, v1.z, v1.w};
    __nv_bfloat16 s0[8], s1[8], s2[8];
    #pragma unroll
    for (int u = 0; u < 8; ++u) {
        float x = xs[u];
        __nv_bfloat16 h1 = __float2bfloat16(x);
        float r1 = __fsub_rn(x, __bfloat162float(h1));
        __nv_bfloat16 h2 = __float2bfloat16(r1);
        float r2 = __fsub_rn(r1, __bfloat162float(h2));
        s0[u] = h1; s1[u] = h2; s2[u] = __float2bfloat16(r2);
    }
    size_t o = tiled_off(k, c8);    // 16B-aligned, 8 elems contiguous
    *reinterpret_cast<uint4*>(g_es0 + o) = *reinterpret_cast<uint4*>(s0);
    *reinterpret_cast<uint4*>(g_es1 + o) = *reinterpret_cast<uint4*>(s1);
    *reinterpret_cast<uint4*>(g_es2 + o) = *reinterpret_cast<uint4*>(s2);
}

// ---------------------------------------------------------------------------
// K3: persistent GEMM + fused argmin. grid=148, 576 threads.
// Tile 256(M, 2 subtiles) x 256(N); D = full 512 TMEM cols (single buffer).
// warps 0-15 (512 thr): epilogue workers; tid 512: MMA consumer; tid 544:
// bulk-copy producer. Producer prefetches next tile's stages during the
// epilogue (slots free once stage MMAs commit; min overwrite distance = 2
// stages -> wait MB_STAGE(gs-2)). Consumer waits MB_EPI (512 arrivals,
// workers' LDTMs done) before overwriting D for the next tile.
// Schedule per kc (A 2 slots X/Y = kc&1, B 3 slots):
//   j:      0      1      2      3      4      5
//   term:  z1e2   z1e3   z1e1   z2e2   z2e1   z3e1
//   aslot:  X      X      X      Y      Y      X
//   bslot:  0      1      2      0      2      2
//   load:  z1,e2   e3     e1     z2     --     z3
// ---------------------------------------------------------------------------
__global__ __launch_bounds__(NTHREADS, 1) void k_mma(const float* __restrict__ emb) {
    extern __shared__ char smem[];
    const int tid = threadIdx.x;

#if HAS_TC
    const uint32_t sbase = smem_u32(smem);
    const int wid = tid >> 5;
    const int lane = tid & 31;

    if (wid == 0) TC_ALLOC(sbase + SM_TMEMPTR, 512);
    if (tid == 0) {
        MBAR_INIT(MB_STAGE(0) + sbase, 1);
        MBAR_INIT(MB_STAGE(1) + sbase, 1);
        #pragma unroll
        for (int q = 0; q < 4; ++q) MBAR_INIT(MB_TMA(q) + sbase, 1);
        MBAR_INIT(MB_DONE + sbase, 1);
        MBAR_INIT(MB_EPI + sbase, 512);
    }
    __syncthreads();
    uint32_t tmem;
    asm volatile("ld.shared.b32 %0, [%1];" : "=r"(tmem) : "r"(sbase + SM_TMEMPTR));

    const int tab_as[6] = {0, 0, 0, 1, 1, 0};
    const int tab_bs[6] = {0, 1, 2, 0, 2, 2};

    if (tid == 512) {
        // ================= consumer: issue MMAs =================
        int ti = 0;
        for (int tile = blockIdx.x; tile < NTILES; tile += GRID_MMA, ++ti) {
            if (ti >= 1) {   // D free once previous tile's epilogue LDTMs done
                MBAR_WAIT(MB_EPI + sbase, (ti - 1) & 1);
            }
            TC_FENCE_AFTER();
            int gs = ti * STAGES_PER_TILE;
            int ln = ti * LOADS_PER_TILE;
            for (int s = 0; s < STAGES_PER_TILE; ++s, ++gs) {
                const int kc = s / 6;
                const int j  = s - kc * 6;
                if (j != 4) {
                    MBAR_WAIT(MB_TMA(ln & 3) + sbase, (ln >> 2) & 1);
                    ++ln;
                }
                const int a_slot = tab_as[j] ^ (kc & 1);
                const int b_slot = tab_bs[j];
                uint64_t bd = mk_desc(sbase + SM_B(b_slot));
                #pragma unroll
                for (int sb2 = 0; sb2 < 2; ++sb2) {
                    uint64_t ad = mk_desc(sbase + SM_A(a_slot) + sb2 * 16384);
                    #pragma unroll
                    for (int k = 0; k < 4; ++k)
                        mma_f16_ss(tmem + sb2 * 256, ad + k * 2, bd + k * 2,
                                   IDESC, (s > 0) || (k > 0));
                }
                TC_COMMIT(MB_STAGE(gs & 1) + sbase);
            }
            // drain this tile's MMAs, then hand D to the workers
            int w = gs - 1;
            MBAR_WAIT(MB_STAGE(w & 1) + sbase, (w >> 1) & 1);
            MBAR_ARRIVE(MB_DONE + sbase);
        }
    } else if (tid == 544) {
        // ================= producer: bulk copies (runs ahead) =================
        int ti = 0;
        for (int tile = blockIdx.x; tile < NTILES; tile += GRID_MMA, ++ti) {
            const int mblk = (tile & (N_MT - 1)) * 2;   // 2 z-blocks of 128
            const int nblk = (tile / N_MT) * 2;         // 2 e-blocks of 128
            int gs = ti * STAGES_PER_TILE;
            int ln = ti * LOADS_PER_TILE;
            for (int s = 0; s < STAGES_PER_TILE; ++s, ++gs) {
                const int kc = s / 6;
                const int j  = s - kc * 6;
                if (j == 4) continue;
                if (gs >= 2) {   // slot-reuse hazard: wait stage gs-2's MMAs
                    int w = gs - 2;
                    MBAR_WAIT(MB_STAGE(w & 1) + sbase, (w >> 1) & 1);
                }
                const uint32_t mb = MB_TMA(ln & 3) + sbase;
                const uint32_t bytes = (j == 0) ? 65536u : 32768u;
                MBAR_EXPECT_TX(mb, bytes);
                const int a_slot = tab_as[j] ^ (kc & 1);
                const int b_slot = tab_bs[j];
                if (j == 0 || j == 3 || j == 5) {   // A load: z1 / z2 / z3
                    const char* src = (j == 0) ? (const char*)g_zs0
                                    : (j == 3) ? (const char*)g_zs1
                                               : (const char*)g_zs2;
                    #pragma unroll
                    for (int sb2 = 0; sb2 < 2; ++sb2)
                        BULK_G2S(sbase + SM_A(a_slot) + sb2 * 16384,
                                 src + ((size_t)((mblk + sb2) * 4 + kc) << 14),
                                 16384u, mb);
                }
                if (j == 0 || j == 1 || j == 2) {   // B load: e2 / e3 / e1
                    const char* src = (j == 0) ? (const char*)g_es1
                                    : (j == 1) ? (const char*)g_es2
                                               : (const char*)g_es0;
                    #pragma unroll
                    for (int nb = 0; nb < 2; ++nb)
                        BULK_G2S(sbase + SM_B(b_slot) + nb * 16384,
                                 src + ((size_t)((nblk + nb) * 4 + kc) << 14),
                                 16384u, mb);
                }
                ++ln;
            }
        }
    } else if (wid < 16) {
        // ================= workers: epilogue =================
        float* cd = reinterpret_cast<float*>(smem + SM_CD);
        int*   ci = reinterpret_cast<int*>(smem + SM_CI);
        const int sub  = (wid >> 2) & 1;
        const int half = wid >> 3;
        const int rl   = (wid & 3) * 32 + lane;

        int ti = 0;
        for (int tile = blockIdx.x; tile < NTILES; tile += GRID_MMA, ++ti) {
            const int m0 = (tile & (N_MT - 1)) * MT;
            const int n_tile = tile / N_MT;
            const int n0 = n_tile * NT;

            MBAR_WAIT(MB_DONE + sbase, ti & 1);
            TC_FENCE_AFTER();

            const float zn = g_znorm[m0 + sub * 128 + rl];
            float bd2 = 3.4e38f;
            int   bi2 = 0;
            #pragma unroll
            for (int jj = 0; jj < 4; ++jj) {
                uint32_t regs[32];
                LDTM_X32(regs, tmem + sub * 256 + half * 128 + jj * 32);
                TC_WAIT_LD();
                #pragma unroll
                for (int c = 0; c < 32; ++c) {
                    int code = n0 + half * 128 + jj * 32 + c;
                    float dot = __uint_as_float(regs[c]);
                    float d = __fmaf_rn(-2.f, dot,
                                        __fadd_rn(zn, __ldg(&g_enorm[code])));
                    if (d < bd2) { bd2 = d; bi2 = code; }
                }
            }
            TC_FENCE_BEFORE();
            MBAR_ARRIVE(MB_EPI + sbase);   // my LDTMs done -> D reusable

            cd[(sub * 128 + rl) * 2 + half] = bd2;
            ci[(sub * 128 + rl) * 2 + half] = bi2;
            asm volatile("bar.sync 1, 512;" ::: "memory");

            if (tid < 256) {
                float d0 = cd[tid * 2], d1 = cd[tid * 2 + 1];
                int   i0 = ci[tid * 2], i1 = ci[tid * 2 + 1];
                if (d1 < d0) { d0 = d1; i0 = i1; }  // half0 first => first-index
                g_cand_d[n_tile * NROWS + m0 + tid] = d0;
                g_cand_i[n_tile * NROWS + m0 + tid] = i0;
            }
            asm volatile("bar.sync 1, 512;" ::: "memory");
        }
    }

    __syncthreads();
    if (wid == 0) {
        TC_RELINQ();
        TC_DEALLOC(tmem, 512);
    }

#else  // ---------------- fallback: fp32 FFMA2 GEMM-argmin ------------------
    float (*As)[260] = reinterpret_cast<float(*)[260]>(smem);
    float (*Bs)[132] = reinterpret_cast<float(*)[132]>(smem + 33280);

    const int tx = tid & 15;
    const int ty = tid >> 4;
    const int lk = tid & 31;
    const int lm = tid >> 5;
    const bool act = tid < 512;

    for (int tile = blockIdx.x; tile < NTILES; tile += GRID_MMA) {
        const int m0 = (tile & (N_MT - 1)) * MT;
        const int n_tile = tile / N_MT;
        const int n0 = n_tile * NT;

        float zn8[8];
        float bestd[8];
        int   besti[8];
        if (act) {
            #pragma unroll
            for (int r = 0; r < 8; ++r) {
                zn8[r] = g_znorm[m0 + ty * 8 + r];
                bestd[r] = 3.4e38f; besti[r] = 0;
            }
        }

        for (int hf = 0; hf < 2; ++hf) {
            const int nb = n0 + hf * 128;
            float2 acc[8][4];
            if (act) {
                #pragma unroll
                for (int r = 0; r < 8; ++r)
                    #pragma unroll
                    for (int j = 0; j < 4; ++j) acc[r][j] = make_float2(0.f, 0.f);
            }

            for (int k0 = 0; k0 < DIM; k0 += 32) {
                __syncthreads();
                if (act) {
                    #pragma unroll
                    for (int j = 0; j < 16; ++j) {
                        int row = lm + j * 16;
                        As[lk][row] = g_zflat[(size_t)(m0 + row) * DIM + k0 + lk];
                    }
                    #pragma unroll
                    for (int j = 0; j < 8; ++j) {
                        int row = lm + j * 16;
                        Bs[lk][row] = emb[(size_t)(nb + row) * DIM + k0 + lk];
                    }
                }
                __syncthreads();
                if (act) {
                    #pragma unroll
                    for (int k = 0; k < 32; ++k) {
                        float4 a0 = *reinterpret_cast<const float4*>(&As[k][ty * 8]);
                        float4 a1 = *reinterpret_cast<const float4*>(&As[k][ty * 8 + 4]);
                        float4 b0 = *reinterpret_cast<const float4*>(&Bs[k][tx * 8]);
                        float4 b1 = *reinterpret_cast<const float4*>(&Bs[k][tx * 8 + 4]);
                        unsigned long long bp0 = pack2(b0.x, b0.y);
                        unsigned long long bp1 = pack2(b0.z, b0.w);
                        unsigned long long bp2 = pack2(b1.x, b1.y);
                        unsigned long long bp3 = pack2(b1.z, b1.w);
                        float av[8] = {a0.x, a0.y, a0.z, a0.w, a1.x, a1.y, a1.z, a1.w};
                        #pragma unroll
                        for (int r = 0; r < 8; ++r) {
                            unsigned long long ap = dup2(av[r]);
                            fma2(acc[r][0], ap, bp0);
                            fma2(acc[r][1], ap, bp1);
                            fma2(acc[r][2], ap, bp2);
                            fma2(acc[r][3], ap, bp3);
                        }
                    }
                }
            }

            if (act) {
                #pragma unroll
                for (int j = 0; j < 8; ++j) {
                    int code = nb + tx * 8 + j;
                    float en = __ldg(&g_enorm[code]);
                    #pragma unroll
                    for (int r = 0; r < 8; ++r) {
                        float dot = (j & 1) ? acc[r][j >> 1].y : acc[r][j >> 1].x;
                        float d = __fmaf_rn(-2.f, dot, __fadd_rn(zn8[r], en));
                        if (d < bestd[r]) { bestd[r] = d; besti[r] = code; }
                    }
                }
            }
        }

        if (act) {
            #pragma unroll
            for (int r = 0; r < 8; ++r) {
                float bd = bestd[r];
                int   bi = besti[r];
                #pragma unroll
                for (int off = 8; off > 0; off >>= 1) {
                    float od = __shfl_down_sync(0xffffffffu, bd, off, 16);
                    int   oi = __shfl_down_sync(0xffffffffu, bi, off, 16);
                    if (od < bd || (od == bd && oi < bi)) { bd = od; bi = oi; }
                }
                if (tx == 0) {
                    int row = m0 + ty * 8 + r;
                    g_cand_d[n_tile * NROWS + row] = bd;
                    g_cand_i[n_tile * NROWS + row] = bi;
                }
            }
        }
        __syncthreads();
    }
#endif
}

// ---------------------------------------------------------------------------
// K4: merge 64 n-chunks per row (ascending => first-index tie-break)
// ---------------------------------------------------------------------------
__global__ void k_merge(float* __restrict__ out, int out_size) {
    int i = blockIdx.x * blockDim.x + threadIdx.x;
    if (i >= NROWS) return;
    float d0 = g_cand_d[i];
    int   i0 = g_cand_i[i];
    for (int s = 1; s < N_NT; ++s) {
        float d1 = g_cand_d[s * NROWS + i];
        int   i1 = g_cand_i[s * NROWS + i];
        if (d1 < d0) { d0 = d1; i0 = i1; }
    }
    g_idx[i] = i0;
    if (out_size > OFF_IDX + i) out[OFF_IDX + i] = (float)i0;
}

// ---------------------------------------------------------------------------
// K5: gather + straight-through + transpose back + loss partials
// ---------------------------------------------------------------------------
__global__ void k_gather(const float* __restrict__ emb, float* __restrict__ out) {
    __shared__ float red[256];
    int n = blockIdx.x, c = threadIdx.x;
    int b = n >> 10, hw = n & 1023;
    int code = g_idx[n];
    float zf = g_zflat[(size_t)n * DIM + c];
    float zq = emb[(size_t)code * DIM + c];
    float diff = __fsub_rn(zq, zf);
    float st = __fadd_rn(zf, diff);
    out[(size_t)(b * 256 + c) * 1024 + hw] = st;
    red[c] = __fmul_rn(diff, diff);
    __syncthreads();
    #pragma unroll
    for (int s = 128; s > 0; s >>= 1) {
        if (c < s) red[c] = __fadd_rn(red[c], red[c + s]);
        __syncthreads();
    }
    if (c == 0) g_losspart[n] = red[0];
}

__global__ void k_loss(float* __restrict__ out, int out_size) {
    __shared__ float red[256];
    int t = threadIdx.x;
    float s = 0.f;
    for (int i = t; i < NROWS; i += 256) s = __fadd_rn(s, g_losspart[i]);
    red[t] = s;
    __syncthreads();
    #pragma unroll
    for (int k = 128; k > 0; k >>= 1) {
        if (t < k) red[t] = __fadd_rn(red[t], red[t + k]);
        __syncthreads();
    }
    if (t == 0 && out_size > OFF_LOSS)
        out[OFF_LOSS] = 1.25f * red[0] / 2097152.0f;
}

// ---------------------------------------------------------------------------
extern "C" void kernel_launch(void* const* d_in, const int* in_sizes, int n_in,
                              void* d_out, int out_size) {
    const float* z   = (const float*)d_in[0];
    const float* emb = (const float*)d_in[1];
    if (n_in >= 2 && in_sizes[0] == NCODES * DIM && in_sizes[1] == NROWS * DIM) {
        const float* t = z; z = emb; emb = t;
    }
    float* out = (float*)d_out;

    cudaFuncSetAttribute(k_mma, cudaFuncAttributeMaxDynamicSharedMemorySize, SMEM_DYN);

    k_transpose<<<dim3(8, 32, 8), dim3(32, 32)>>>(z);
    k_norms<<<(NROWS + NCODES + 255) / 256, 256>>>(emb);
    k_split_e<<<(NCODES * DIM / 8 + 255) / 256, 256>>>(emb);
    k_mma<<<GRID_MMA, NTHREADS, SMEM_DYN>>>(emb);
    k_merge<<<NROWS / 256, 256>>>(out, out_size);
    k_gather<<<NROWS, 256>>>(emb, out);
    k_loss<<<1, 256>>>(out, out_size);
}

// round 12
// speedup vs baseline: 1.3171x; 1.0043x over previous
#include <cuda_runtime.h>
#include <cuda_bf16.h>
#include <cstdint>

// ---------------------------------------------------------------------------
// VectorQuantizer. tcgen05 bf16 6-term split GEMM + fused argmin (sm_103a),
// fp32 FFMA2 fallback (plain sm_103 pass). 256x256 tiles, persistent CTAs,
// bulk-async staging with precise per-slot hazard waits. Stage-commit ring
// DEPTH 8: ring 4 alias-hangs for hazard distance 6 (parity bit flips back
// after two completions on one slot -> producer waits for a stage whose load
// it must itself issue). Ring 8 needs consumer to run 8 stages past the
// waited stage to alias -> impossible (>= 2 stages into unissued loads).
// ---------------------------------------------------------------------------

#if defined(__CUDA_ARCH__) && (defined(__CUDA_ARCH_FEAT_SM103_ALL) || \
    defined(__CUDA_ARCH_FEAT_SM100_ALL) || defined(__CUDA_ARCH_FAMILY_SPECIFIC__))
#define HAS_TC 1
#else
#define HAS_TC 0
#endif

#define NROWS   8192
#define NCODES  16384
#define DIM     256
#define NZQ     2097152
#define OFF_LOSS NZQ
#define OFF_IDX  (NZQ + 1)

#define MT 256
#define NT 256
#define N_MT (NROWS / MT)     // 32
#define N_NT (NCODES / NT)    // 64
#define NTILES (N_MT * N_NT)  // 2048
#define GRID_MMA 148
#define NTHREADS 576          // 16 worker warps + consumer + producer
#define KC 64
#define STAGES_PER_TILE 24    // 4 kc x 6 terms
#define LOADS_PER_TILE 20

// ---- dynamic smem layout (bytes): A slots 2x32KB, B slots 3x32KB ----
#define SM_A(s)    ((s) * 32768)
#define SM_B(s)    (65536 + (s) * 32768)
#define SM_CD      163840                    // float cand[2][256][2]
#define SM_CI      (SM_CD + 4096)            // int   cand[2][256][2]
#define SM_TMEMPTR (SM_CI + 4096)
#define SM_MB      (SM_TMEMPTR + 8)
// mbar map: [0,64) stage ring(8)  [64,128) tma ring(8)  [128,144) tile ring(2)
//           [144,152) epi
#define MB_STAGE(i) (SM_MB + (i) * 8)
#define MB_TMA(i)   (SM_MB + 64 + (i) * 8)
#define MB_TILE(i)  (SM_MB + 128 + (i) * 8)
#define MB_EPI      (SM_MB + 144)
#define SMEM_DYN   (SM_MB + 160)

// idesc kind::f16: F32 acc(1<<4), A=BF16(1<<7), B=BF16(1<<10), N/8<<17, M/16<<24
#define IDESC 0x8400490u   // M=128, N=256

static __device__ __forceinline__ uint32_t smem_u32(const void* p) {
    return (uint32_t)__cvta_generic_to_shared(p);
}

// ---- device scratch ----
__device__ float g_zflat[NROWS * DIM];
__device__ float g_znorm[NROWS];
__device__ float g_enorm[NCODES];
// splits pre-swizzled: [block128][kc(4)][8192 bf16 = 16KB SW128 tile]
__device__ __nv_bfloat16 g_zs0[NROWS * DIM];
__device__ __nv_bfloat16 g_zs1[NROWS * DIM];
__device__ __nv_bfloat16 g_zs2[NROWS * DIM];
__device__ __nv_bfloat16 g_es0[NCODES * DIM];
__device__ __nv_bfloat16 g_es1[NCODES * DIM];
__device__ __nv_bfloat16 g_es2[NCODES * DIM];
__device__ float g_cand_d[N_NT * NROWS];
__device__ int   g_cand_i[N_NT * NROWS];
__device__ int   g_idx[NROWS];
__device__ float g_losspart[NROWS];

// tiled offset for (row n, col c) within a split array (element index)
static __device__ __forceinline__ size_t tiled_off(int n, int c) {
    int blk = n >> 7, r = n & 127, kc = c >> 6, cc = c & 63;
    return ((size_t)((blk << 2) + kc) << 13) + (size_t)r * 64 + (cc ^ ((r & 7) << 3));
}

// ---- packed f32x2 helpers (fallback path) ----
__device__ __forceinline__ unsigned long long pack2(float x, float y) {
    unsigned long long u;
    asm("mov.b64 %0, {%1, %2};" : "=l"(u)
        : "r"(__float_as_uint(x)), "r"(__float_as_uint(y)));
    return u;
}
__device__ __forceinline__ unsigned long long dup2(float x) {
    unsigned long long u;
    unsigned int r = __float_as_uint(x);
    asm("mov.b64 %0, {%1, %1};" : "=l"(u) : "r"(r));
    return u;
}
__device__ __forceinline__ void fma2(float2& d, unsigned long long a, unsigned long long b) {
    unsigned long long* dp = reinterpret_cast<unsigned long long*>(&d);
    asm("fma.rn.f32x2 %0, %1, %2, %0;" : "+l"(*dp) : "l"(a), "l"(b));
}

#if HAS_TC
#define MBAR_INIT(a, c) \
    asm volatile("mbarrier.init.shared.b64 [%0], %1;" :: "r"(a), "r"(c) : "memory")

#define MBAR_ARRIVE(a) \
    asm volatile("mbarrier.arrive.shared.b64 _, [%0];" :: "r"(a) : "memory")

#define MBAR_WAIT(a, par) do {                                               \
    asm volatile(                                                            \
        "{\n\t.reg .pred P1;\n\t"                                            \
        "WAIT_LOOP_%=:\n\t"                                                  \
        "mbarrier.try_wait.parity.acquire.cta.shared::cta.b64 P1, [%0], %1, 0x989680;\n\t" \
        "@P1 bra.uni WAIT_DONE_%=;\n\t"                                      \
        "bra.uni WAIT_LOOP_%=;\n\t"                                          \
        "WAIT_DONE_%=:\n\t}"                                                 \
        :: "r"(a), "r"(par) : "memory");                                     \
} while (0)

#define MBAR_EXPECT_TX(a, bytes) \
    asm volatile("mbarrier.arrive.expect_tx.shared.b64 _, [%0], %1;" \
                 :: "r"(a), "r"(bytes) : "memory")

#define BULK_G2S(dst, src, sz, mbar) \
    asm volatile("cp.async.bulk.shared::cta.global.mbarrier::complete_tx::bytes " \
                 "[%0], [%1], %2, [%3];" \
                 :: "r"(dst), "l"(src), "r"(sz), "r"(mbar) : "memory")

#define TC_ALLOC(smem_addr, ncols) \
    asm volatile("tcgen05.alloc.cta_group::1.sync.aligned.shared::cta.b32 [%0], %1;" \
                 :: "r"(smem_addr), "r"(ncols) : "memory")
#define TC_DEALLOC(tmem, ncols) \
    asm volatile("tcgen05.dealloc.cta_group::1.sync.aligned.b32 %0, %1;" :: "r"(tmem), "r"(ncols))
#define TC_RELINQ() \
    asm volatile("tcgen05.relinquish_alloc_permit.cta_group::1.sync.aligned;")
#define TC_COMMIT(mbar) \
    asm volatile("tcgen05.commit.cta_group::1.mbarrier::arrive::one.shared::cluster.b64 [%0];" \
                 :: "r"(mbar) : "memory")
#define TC_FENCE_AFTER()  asm volatile("tcgen05.fence::after_thread_sync;" ::: "memory")
#define TC_FENCE_BEFORE() asm volatile("tcgen05.fence::before_thread_sync;" ::: "memory")
#define TC_WAIT_LD()      asm volatile("tcgen05.wait::ld.sync.aligned;" ::: "memory")

static __device__ __forceinline__ void mma_f16_ss(
    uint32_t d_tmem, uint64_t a_desc, uint64_t b_desc, uint32_t idesc, bool acc)
{
    uint32_t en = acc ? 1u : 0u;
    asm volatile(
        "{\n\t.reg .pred p;\n\t"
        "setp.ne.u32 p, %4, 0;\n\t"
        "tcgen05.mma.cta_group::1.kind::f16 [%0], %1, %2, %3, {%5, %5, %5, %5}, p;\n\t"
        "}"
        :: "r"(d_tmem), "l"(a_desc), "l"(b_desc), "r"(idesc), "r"(en), "r"(0u)
        : "memory");
}

#define DESC_BASE ((2ULL << 61) | (1ULL << 46) | (64ULL << 32) | (1ULL << 16))
static __device__ __forceinline__ uint64_t mk_desc(uint32_t addr) {
    return DESC_BASE | ((uint64_t)(addr >> 4) & 0x3FFF);
}

#define LDTM_X32(r, a)                                                        \
    asm volatile("tcgen05.ld.sync.aligned.32x32b.x32.b32 "                    \
        "{%0,%1,%2,%3,%4,%5,%6,%7,%8,%9,%10,%11,%12,%13,%14,%15,"             \
        "%16,%17,%18,%19,%20,%21,%22,%23,%24,%25,%26,%27,%28,%29,%30,%31}, [%32];" \
        : "=r"((r)[0]),"=r"((r)[1]),"=r"((r)[2]),"=r"((r)[3]),                \
          "=r"((r)[4]),"=r"((r)[5]),"=r"((r)[6]),"=r"((r)[7]),                \
          "=r"((r)[8]),"=r"((r)[9]),"=r"((r)[10]),"=r"((r)[11]),              \
          "=r"((r)[12]),"=r"((r)[13]),"=r"((r)[14]),"=r"((r)[15]),            \
          "=r"((r)[16]),"=r"((r)[17]),"=r"((r)[18]),"=r"((r)[19]),            \
          "=r"((r)[20]),"=r"((r)[21]),"=r"((r)[22]),"=r"((r)[23]),            \
          "=r"((r)[24]),"=r"((r)[25]),"=r"((r)[26]),"=r"((r)[27]),            \
          "=r"((r)[28]),"=r"((r)[29]),"=r"((r)[30]),"=r"((r)[31])             \
        : "r"(a))
#endif // HAS_TC

// ---------------------------------------------------------------------------
// K0: transpose z (b,c,h,w) -> zflat[row][c] + bf16 3-split into tiled layout
// ---------------------------------------------------------------------------
__global__ void k_transpose(const float* __restrict__ z) {
    __shared__ float t[32][33];
    int b = blockIdx.z, h = blockIdx.y, c0 = blockIdx.x * 32;
    int tx = threadIdx.x, ty = threadIdx.y;
    t[ty][tx] = z[((size_t)(b * 256 + c0 + ty) * 32 + h) * 32 + tx];
    __syncthreads();
    int n = b * 1024 + h * 32 + ty;
    int c = c0 + tx;
    float x = t[tx][ty];
    g_zflat[(size_t)n * DIM + c] = x;
    __nv_bfloat16 h1 = __float2bfloat16(x);
    float r1 = __fsub_rn(x, __bfloat162float(h1));
    __nv_bfloat16 h2 = __float2bfloat16(r1);
    float r2 = __fsub_rn(r1, __bfloat162float(h2));
    size_t o = tiled_off(n, c);
    g_zs0[o] = h1; g_zs1[o] = h2; g_zs2[o] = __float2bfloat16(r2);
}

// ---------------------------------------------------------------------------
// K1: row norms (reference elementwise square + k-ascending sum rounding)
// ---------------------------------------------------------------------------
__global__ void k_norms(const float* __restrict__ emb) {
    int i = blockIdx.x * blockDim.x + threadIdx.x;
    if (i < NROWS) {
        const float4* p = reinterpret_cast<const float4*>(g_zflat + (size_t)i * DIM);
        float s = 0.f;
        #pragma unroll 8
        for (int c = 0; c < DIM / 4; ++c) {
            float4 v = p[c];
            s = __fadd_rn(s, __fmul_rn(v.x, v.x));
            s = __fadd_rn(s, __fmul_rn(v.y, v.y));
            s = __fadd_rn(s, __fmul_rn(v.z, v.z));
            s = __fadd_rn(s, __fmul_rn(v.w, v.w));
        }
        g_znorm[i] = s;
    } else if (i < NROWS + NCODES) {
        int k = i - NROWS;
        const float4* p = reinterpret_cast<const float4*>(emb + (size_t)k * DIM);
        float s = 0.f;
        #pragma unroll 8
        for (int c = 0; c < DIM / 4; ++c) {
            float4 v = p[c];
            s = __fadd_rn(s, __fmul_rn(v.x, v.x));
            s = __fadd_rn(s, __fmul_rn(v.y, v.y));
            s = __fadd_rn(s, __fmul_rn(v.z, v.z));
            s = __fadd_rn(s, __fmul_rn(v.w, v.w));
        }
        g_enorm[k] = s;
    }
}

// ---------------------------------------------------------------------------
// K2: embedding bf16 3-way split, vectorized 8 elements/thread.
// ---------------------------------------------------------------------------
__global__ void k_split_e(const float* __restrict__ emb) {
    int i = blockIdx.x * blockDim.x + threadIdx.x;     // i indexes groups of 8
    if (i >= NCODES * DIM / 8) return;
    int k = i >> 5, c8 = (i & 31) * 8;
    const float4* src = reinterpret_cast<const float4*>(emb + (size_t)k * DIM + c8);
    float4 v0 = src[0], v1 = src[1];
    float xs[8] = {v0.x, v0.y, v0.z, v0.w, v1.x, v1.y, v1.z, v1.w};
    __nv_bfloat16 s0[8], s1[8], s2[8];
    #pragma unroll
    for (int u = 0; u < 8; ++u) {
        float x = xs[u];
        __nv_bfloat16 h1 = __float2bfloat16(x);
        float r1 = __fsub_rn(x, __bfloat162float(h1));
        __nv_bfloat16 h2 = __float2bfloat16(r1);
        float r2 = __fsub_rn(r1, __bfloat162float(h2));
        s0[u] = h1; s1[u] = h2; s2[u] = __float2bfloat16(r2);
    }
    size_t o = tiled_off(k, c8);    // 16B-aligned, 8 elems contiguous
    *reinterpret_cast<uint4*>(g_es0 + o) = *reinterpret_cast<uint4*>(s0);
    *reinterpret_cast<uint4*>(g_es1 + o) = *reinterpret_cast<uint4*>(s1);
    *reinterpret_cast<uint4*>(g_es2 + o) = *reinterpret_cast<uint4*>(s2);
}

// ---------------------------------------------------------------------------
// K3: persistent GEMM + fused argmin. grid=148, 576 threads.
// Schedule per kc (A 2 slots X/Y = kc&1, B 3 slots):
//   j:      0      1      2      3      4      5
//   term:  z1e2   z1e3   z1e1   z2e2   z2e1   z3e1
//   aslot:  X      X      X      Y      Y      X
//   bslot:  0      1      2      0      2      2
//   load:  z1,e2   e3     e1     z2     --     z3
// Per-load hazard distance: j0:2 (covers B0's 3) j1:6 j2:3 j3:4 j5:3.
// Producer waits MB_STAGE((gs-d)&7) parity ((gs-d)>>3)&1 — ring 8 cannot
// alias for d<=8. TMA ring 8. Last stage dual-commits to MB_TILE(ti&1);
// workers wait it directly; consumer proceeds after MB_EPI (512 arrivals).
// ---------------------------------------------------------------------------
__global__ __launch_bounds__(NTHREADS, 1) void k_mma(const float* __restrict__ emb) {
    extern __shared__ char smem[];
    const int tid = threadIdx.x;

#if HAS_TC
    const uint32_t sbase = smem_u32(smem);
    const int wid = tid >> 5;
    const int lane = tid & 31;

    if (wid == 0) TC_ALLOC(sbase + SM_TMEMPTR, 512);
    if (tid == 0) {
        #pragma unroll
        for (int q = 0; q < 8; ++q) MBAR_INIT(MB_STAGE(q) + sbase, 1);
        #pragma unroll
        for (int q = 0; q < 8; ++q) MBAR_INIT(MB_TMA(q) + sbase, 1);
        MBAR_INIT(MB_TILE(0) + sbase, 1);
        MBAR_INIT(MB_TILE(1) + sbase, 1);
        MBAR_INIT(MB_EPI + sbase, 512);
    }
    __syncthreads();
    uint32_t tmem;
    asm volatile("ld.shared.b32 %0, [%1];" : "=r"(tmem) : "r"(sbase + SM_TMEMPTR));

    const int tab_as[6] = {0, 0, 0, 1, 1, 0};
    const int tab_bs[6] = {0, 1, 2, 0, 2, 2};
    const int tab_d[6]  = {2, 6, 3, 4, 0, 3};   // hazard distances

    if (tid == 512) {
        // ================= consumer: issue MMAs (never drains) ==============
        int ti = 0;
        for (int tile = blockIdx.x; tile < NTILES; tile += GRID_MMA, ++ti) {
            if (ti >= 1) {   // D free once previous tile's epilogue LDTMs done
                MBAR_WAIT(MB_EPI + sbase, (ti - 1) & 1);
            }
            TC_FENCE_AFTER();
            int gs = ti * STAGES_PER_TILE;
            int ln = ti * LOADS_PER_TILE;
            for (int s = 0; s < STAGES_PER_TILE; ++s, ++gs) {
                const int kc = s / 6;
                const int j  = s - kc * 6;
                if (j != 4) {
                    MBAR_WAIT(MB_TMA(ln & 7) + sbase, (ln >> 3) & 1);
                    ++ln;
                }
                const int a_slot = tab_as[j] ^ (kc & 1);
                const int b_slot = tab_bs[j];
                uint64_t bd = mk_desc(sbase + SM_B(b_slot));
                #pragma unroll
                for (int sb2 = 0; sb2 < 2; ++sb2) {
                    uint64_t ad = mk_desc(sbase + SM_A(a_slot) + sb2 * 16384);
                    #pragma unroll
                    for (int k = 0; k < 4; ++k)
                        mma_f16_ss(tmem + sb2 * 256, ad + k * 2, bd + k * 2,
                                   IDESC, (s > 0) || (k > 0));
                }
                TC_COMMIT(MB_STAGE(gs & 7) + sbase);
                if (s == STAGES_PER_TILE - 1)
                    TC_COMMIT(MB_TILE(ti & 1) + sbase);   // tile handoff
            }
        }
    } else if (tid == 544) {
        // ============ producer: bulk copies, per-slot hazard waits ==========
        int ti = 0;
        for (int tile = blockIdx.x; tile < NTILES; tile += GRID_MMA, ++ti) {
            const int mblk = (tile & (N_MT - 1)) * 2;   // 2 z-blocks of 128
            const int nblk = (tile / N_MT) * 2;         // 2 e-blocks of 128
            int gs = ti * STAGES_PER_TILE;
            int ln = ti * LOADS_PER_TILE;
            for (int s = 0; s < STAGES_PER_TILE; ++s, ++gs) {
                const int kc = s / 6;
                const int j  = s - kc * 6;
                if (j == 4) continue;
                const int h = gs - tab_d[j];
                if (h >= 0) MBAR_WAIT(MB_STAGE(h & 7) + sbase, (h >> 3) & 1);
                const uint32_t mb = MB_TMA(ln & 7) + sbase;
                const uint32_t bytes = (j == 0) ? 65536u : 32768u;
                MBAR_EXPECT_TX(mb, bytes);
                const int a_slot = tab_as[j] ^ (kc & 1);
                const int b_slot = tab_bs[j];
                if (j == 0 || j == 3 || j == 5) {   // A load: z1 / z2 / z3
                    const char* src = (j == 0) ? (const char*)g_zs0
                                    : (j == 3) ? (const char*)g_zs1
                                               : (const char*)g_zs2;
                    #pragma unroll
                    for (int sb2 = 0; sb2 < 2; ++sb2)
                        BULK_G2S(sbase + SM_A(a_slot) + sb2 * 16384,
                                 src + ((size_t)((mblk + sb2) * 4 + kc) << 14),
                                 16384u, mb);
                }
                if (j == 0 || j == 1 || j == 2) {   // B load: e2 / e3 / e1
                    const char* src = (j == 0) ? (const char*)g_es1
                                    : (j == 1) ? (const char*)g_es2
                                               : (const char*)g_es0;
                    #pragma unroll
                    for (int nb = 0; nb < 2; ++nb)
                        BULK_G2S(sbase + SM_B(b_slot) + nb * 16384,
                                 src + ((size_t)((nblk + nb) * 4 + kc) << 14),
                                 16384u, mb);
                }
                ++ln;
            }
        }
    } else if (wid < 16) {
        // ================= workers: epilogue =================
        const int sub  = (wid >> 2) & 1;
        const int half = wid >> 3;
        const int rl   = (wid & 3) * 32 + lane;

        int ti = 0;
        for (int tile = blockIdx.x; tile < NTILES; tile += GRID_MMA, ++ti) {
            const int m0 = (tile & (N_MT - 1)) * MT;
            const int n_tile = tile / N_MT;
            const int n0 = n_tile * NT;
            float* cd = reinterpret_cast<float*>(smem + SM_CD) + (ti & 1) * 512;
            int*   ci = reinterpret_cast<int*>(smem + SM_CI) + (ti & 1) * 512;

            MBAR_WAIT(MB_TILE(ti & 1) + sbase, (ti >> 1) & 1);
            TC_FENCE_AFTER();

            const float zn = g_znorm[m0 + sub * 128 + rl];
            float bd2 = 3.4e38f;
            int   bi2 = 0;
            #pragma unroll
            for (int jj = 0; jj < 4; ++jj) {
                uint32_t regs[32];
                LDTM_X32(regs, tmem + sub * 256 + half * 128 + jj * 32);
                TC_WAIT_LD();
                #pragma unroll
                for (int c = 0; c < 32; ++c) {
                    int code = n0 + half * 128 + jj * 32 + c;
                    float dot = __uint_as_float(regs[c]);
                    float d = __fmaf_rn(-2.f, dot,
                                        __fadd_rn(zn, __ldg(&g_enorm[code])));
                    if (d < bd2) { bd2 = d; bi2 = code; }
                }
            }
            TC_FENCE_BEFORE();
            MBAR_ARRIVE(MB_EPI + sbase);   // my LDTMs done -> D reusable

            cd[(sub * 128 + rl) * 2 + half] = bd2;
            ci[(sub * 128 + rl) * 2 + half] = bi2;
            asm volatile("bar.sync 1, 512;" ::: "memory");

            if (tid < 256) {
                float d0 = cd[tid * 2], d1 = cd[tid * 2 + 1];
                int   i0 = ci[tid * 2], i1 = ci[tid * 2 + 1];
                if (d1 < d0) { d0 = d1; i0 = i1; }  // half0 first => first-index
                g_cand_d[n_tile * NROWS + m0 + tid] = d0;
                g_cand_i[n_tile * NROWS + m0 + tid] = i0;
            }
            // next tile uses the other cd/ci buffer; its bar.sync separates
            // this reduce from the writes two tiles later.
        }
    }

    __syncthreads();
    if (wid == 0) {
        TC_RELINQ();
        TC_DEALLOC(tmem, 512);
    }

#else  // ---------------- fallback: fp32 FFMA2 GEMM-argmin ------------------
    float (*As)[260] = reinterpret_cast<float(*)[260]>(smem);
    float (*Bs)[132] = reinterpret_cast<float(*)[132]>(smem + 33280);

    const int tx = tid & 15;
    const int ty = tid >> 4;
    const int lk = tid & 31;
    const int lm = tid >> 5;
    const bool act = tid < 512;

    for (int tile = blockIdx.x; tile < NTILES; tile += GRID_MMA) {
        const int m0 = (tile & (N_MT - 1)) * MT;
        const int n_tile = tile / N_MT;
        const int n0 = n_tile * NT;

        float zn8[8];
        float bestd[8];
        int   besti[8];
        if (act) {
            #pragma unroll
            for (int r = 0; r < 8; ++r) {
                zn8[r] = g_znorm[m0 + ty * 8 + r];
                bestd[r] = 3.4e38f; besti[r] = 0;
            }
        }

        for (int hf = 0; hf < 2; ++hf) {
            const int nb = n0 + hf * 128;
            float2 acc[8][4];
            if (act) {
                #pragma unroll
                for (int r = 0; r < 8; ++r)
                    #pragma unroll
                    for (int j = 0; j < 4; ++j) acc[r][j] = make_float2(0.f, 0.f);
            }

            for (int k0 = 0; k0 < DIM; k0 += 32) {
                __syncthreads();
                if (act) {
                    #pragma unroll
                    for (int j = 0; j < 16; ++j) {
                        int row = lm + j * 16;
                        As[lk][row] = g_zflat[(size_t)(m0 + row) * DIM + k0 + lk];
                    }
                    #pragma unroll
                    for (int j = 0; j < 8; ++j) {
                        int row = lm + j * 16;
                        Bs[lk][row] = emb[(size_t)(nb + row) * DIM + k0 + lk];
                    }
                }
                __syncthreads();
                if (act) {
                    #pragma unroll
                    for (int k = 0; k < 32; ++k) {
                        float4 a0 = *reinterpret_cast<const float4*>(&As[k][ty * 8]);
                        float4 a1 = *reinterpret_cast<const float4*>(&As[k][ty * 8 + 4]);
                        float4 b0 = *reinterpret_cast<const float4*>(&Bs[k][tx * 8]);
                        float4 b1 = *reinterpret_cast<const float4*>(&Bs[k][tx * 8 + 4]);
                        unsigned long long bp0 = pack2(b0.x, b0.y);
                        unsigned long long bp1 = pack2(b0.z, b0.w);
                        unsigned long long bp2 = pack2(b1.x, b1.y);
                        unsigned long long bp3 = pack2(b1.z, b1.w);
                        float av[8] = {a0.x, a0.y, a0.z, a0.w, a1.x, a1.y, a1.z, a1.w};
                        #pragma unroll
                        for (int r = 0; r < 8; ++r) {
                            unsigned long long ap = dup2(av[r]);
                            fma2(acc[r][0], ap, bp0);
                            fma2(acc[r][1], ap, bp1);
                            fma2(acc[r][2], ap, bp2);
                            fma2(acc[r][3], ap, bp3);
                        }
                    }
                }
            }

            if (act) {
                #pragma unroll
                for (int j = 0; j < 8; ++j) {
                    int code = nb + tx * 8 + j;
                    float en = __ldg(&g_enorm[code]);
                    #pragma unroll
                    for (int r = 0; r < 8; ++r) {
                        float dot = (j & 1) ? acc[r][j >> 1].y : acc[r][j >> 1].x;
                        float d = __fmaf_rn(-2.f, dot, __fadd_rn(zn8[r], en));
                        if (d < bestd[r]) { bestd[r] = d; besti[r] = code; }
                    }
                }
            }
        }

        if (act) {
            #pragma unroll
            for (int r = 0; r < 8; ++r) {
                float bd = bestd[r];
                int   bi = besti[r];
                #pragma unroll
                for (int off = 8; off > 0; off >>= 1) {
                    float od = __shfl_down_sync(0xffffffffu, bd, off, 16);
                    int   oi = __shfl_down_sync(0xffffffffu, bi, off, 16);
                    if (od < bd || (od == bd && oi < bi)) { bd = od; bi = oi; }
                }
                if (tx == 0) {
                    int row = m0 + ty * 8 + r;
                    g_cand_d[n_tile * NROWS + row] = bd;
                    g_cand_i[n_tile * NROWS + row] = bi;
                }
            }
        }
        __syncthreads();
    }
#endif
}

// ---------------------------------------------------------------------------
// K4: merge 64 n-chunks per row (ascending => first-index tie-break)
// ---------------------------------------------------------------------------
__global__ void k_merge(float* __restrict__ out, int out_size) {
    int i = blockIdx.x * blockDim.x + threadIdx.x;
    if (i >= NROWS) return;
    float d0 = g_cand_d[i];
    int   i0 = g_cand_i[i];
    for (int s = 1; s < N_NT; ++s) {
        float d1 = g_cand_d[s * NROWS + i];
        int   i1 = g_cand_i[s * NROWS + i];
        if (d1 < d0) { d0 = d1; i0 = i1; }
    }
    g_idx[i] = i0;
    if (out_size > OFF_IDX + i) out[OFF_IDX + i] = (float)i0;
}

// ---------------------------------------------------------------------------
// K5: gather + straight-through + transpose back + loss partials
// ---------------------------------------------------------------------------
__global__ void k_gather(const float* __restrict__ emb, float* __restrict__ out) {
    __shared__ float red[256];
    int n = blockIdx.x, c = threadIdx.x;
    int b = n >> 10, hw = n & 1023;
    int code = g_idx[n];
    float zf = g_zflat[(size_t)n * DIM + c];
    float zq = emb[(size_t)code * DIM + c];
    float diff = __fsub_rn(zq, zf);
    float st = __fadd_rn(zf, diff);
    out[(size_t)(b * 256 + c) * 1024 + hw] = st;
    red[c] = __fmul_rn(diff, diff);
    __syncthreads();
    #pragma unroll
    for (int s = 128; s > 0; s >>= 1) {
        if (c < s) red[c] = __fadd_rn(red[c], red[c + s]);
        __syncthreads();
    }
    if (c == 0) g_losspart[n] = red[0];
}

__global__ void k_loss(float* __restrict__ out, int out_size) {
    __shared__ float red[256];
    int t = threadIdx.x;
    float s = 0.f;
    for (int i = t; i < NROWS; i += 256) s = __fadd_rn(s, g_losspart[i]);
    red[t] = s;
    __syncthreads();
    #pragma unroll
    for (int k = 128; k > 0; k >>= 1) {
        if (t < k) red[t] = __fadd_rn(red[t], red[t + k]);
        __syncthreads();
    }
    if (t == 0 && out_size > OFF_LOSS)
        out[OFF_LOSS] = 1.25f * red[0] / 2097152.0f;
}

// ---------------------------------------------------------------------------
extern "C" void kernel_launch(void* const* d_in, const int* in_sizes, int n_in,
                              void* d_out, int out_size) {
    const float* z   = (const float*)d_in[0];
    const float* emb = (const float*)d_in[1];
    if (n_in >= 2 && in_sizes[0] == NCODES * DIM && in_sizes[1] == NROWS * DIM) {
        const float* t = z; z = emb; emb = t;
    }
    float* out = (float*)d_out;

    cudaFuncSetAttribute(k_mma, cudaFuncAttributeMaxDynamicSharedMemorySize, SMEM_DYN);

    k_transpose<<<dim3(8, 32, 8), dim3(32, 32)>>>(z);
    k_norms<<<(NROWS + NCODES + 255) / 256, 256>>>(emb);
    k_split_e<<<(NCODES * DIM / 8 + 255) / 256, 256>>>(emb);
    k_mma<<<GRID_MMA, NTHREADS, SMEM_DYN>>>(emb);
    k_merge<<<NROWS / 256, 256>>>(out, out_size);
    k_gather<<<NROWS, 256>>>(emb, out);
    k_loss<<<1, 256>>>(out, out_size);
}

// round 13
// speedup vs baseline: 1.3430x; 1.0196x over previous
#include <cuda_runtime.h>
#include <cuda_bf16.h>
#include <cstdint>

// ---------------------------------------------------------------------------
// VectorQuantizer. tcgen05 bf16 6-term split GEMM + fused argmin (sm_103a),
// fp32 FFMA2 fallback (plain sm_103 pass). 256x256 tiles, persistent CTAs,
// bulk-async staging with precise per-slot hazard waits (stage ring 8).
// NEW: subtile-pipelined epilogue — EPI split per M-subtile; consumer issues
// next tile's sub0 MMAs as soon as sub0's D columns are drained, overlapping
// roughly half the LDTM/argmin epilogue with tensor work. Merge fused into
// gather kernel.
// ---------------------------------------------------------------------------

#if defined(__CUDA_ARCH__) && (defined(__CUDA_ARCH_FEAT_SM103_ALL) || \
    defined(__CUDA_ARCH_FEAT_SM100_ALL) || defined(__CUDA_ARCH_FAMILY_SPECIFIC__))
#define HAS_TC 1
#else
#define HAS_TC 0
#endif

#define NROWS   8192
#define NCODES  16384
#define DIM     256
#define NZQ     2097152
#define OFF_LOSS NZQ
#define OFF_IDX  (NZQ + 1)

#define MT 256
#define NT 256
#define N_MT (NROWS / MT)     // 32
#define N_NT (NCODES / NT)    // 64
#define NTILES (N_MT * N_NT)  // 2048
#define GRID_MMA 148
#define NTHREADS 576          // 16 worker warps + consumer + producer
#define KC 64
#define STAGES_PER_TILE 24    // 4 kc x 6 terms
#define LOADS_PER_TILE 20

// ---- dynamic smem layout (bytes): A slots 2x32KB, B slots 3x32KB ----
#define SM_A(s)    ((s) * 32768)
#define SM_B(s)    (65536 + (s) * 32768)
#define SM_CD      163840                    // float cand[2][256][2]
#define SM_CI      (SM_CD + 4096)            // int   cand[2][256][2]
#define SM_TMEMPTR (SM_CI + 4096)
#define SM_MB      (SM_TMEMPTR + 8)
// mbar map: [0,64) stage ring(8)  [64,128) tma ring(8)  [128,144) tile ring(2)
//           [144,152) epi0  [152,160) epi1
#define MB_STAGE(i) (SM_MB + (i) * 8)
#define MB_TMA(i)   (SM_MB + 64 + (i) * 8)
#define MB_TILE(i)  (SM_MB + 128 + (i) * 8)
#define MB_EPI0     (SM_MB + 144)
#define MB_EPI1     (SM_MB + 152)
#define SMEM_DYN   (SM_MB + 168)

// idesc kind::f16: F32 acc(1<<4), A=BF16(1<<7), B=BF16(1<<10), N/8<<17, M/16<<24
#define IDESC 0x8400490u   // M=128, N=256

static __device__ __forceinline__ uint32_t smem_u32(const void* p) {
    return (uint32_t)__cvta_generic_to_shared(p);
}

// ---- device scratch ----
__device__ float g_zflat[NROWS * DIM];
__device__ float g_znorm[NROWS];
__device__ float g_enorm[NCODES];
// splits pre-swizzled: [block128][kc(4)][8192 bf16 = 16KB SW128 tile]
__device__ __nv_bfloat16 g_zs0[NROWS * DIM];
__device__ __nv_bfloat16 g_zs1[NROWS * DIM];
__device__ __nv_bfloat16 g_zs2[NROWS * DIM];
__device__ __nv_bfloat16 g_es0[NCODES * DIM];
__device__ __nv_bfloat16 g_es1[NCODES * DIM];
__device__ __nv_bfloat16 g_es2[NCODES * DIM];
__device__ float g_cand_d[N_NT * NROWS];
__device__ int   g_cand_i[N_NT * NROWS];
__device__ float g_losspart[NROWS];

// tiled offset for (row n, col c) within a split array (element index)
static __device__ __forceinline__ size_t tiled_off(int n, int c) {
    int blk = n >> 7, r = n & 127, kc = c >> 6, cc = c & 63;
    return ((size_t)((blk << 2) + kc) << 13) + (size_t)r * 64 + (cc ^ ((r & 7) << 3));
}

// ---- packed f32x2 helpers (fallback path) ----
__device__ __forceinline__ unsigned long long pack2(float x, float y) {
    unsigned long long u;
    asm("mov.b64 %0, {%1, %2};" : "=l"(u)
        : "r"(__float_as_uint(x)), "r"(__float_as_uint(y)));
    return u;
}
__device__ __forceinline__ unsigned long long dup2(float x) {
    unsigned long long u;
    unsigned int r = __float_as_uint(x);
    asm("mov.b64 %0, {%1, %1};" : "=l"(u) : "r"(r));
    return u;
}
__device__ __forceinline__ void fma2(float2& d, unsigned long long a, unsigned long long b) {
    unsigned long long* dp = reinterpret_cast<unsigned long long*>(&d);
    asm("fma.rn.f32x2 %0, %1, %2, %0;" : "+l"(*dp) : "l"(a), "l"(b));
}

#if HAS_TC
#define MBAR_INIT(a, c) \
    asm volatile("mbarrier.init.shared.b64 [%0], %1;" :: "r"(a), "r"(c) : "memory")

#define MBAR_ARRIVE(a) \
    asm volatile("mbarrier.arrive.shared.b64 _, [%0];" :: "r"(a) : "memory")

#define MBAR_WAIT(a, par) do {                                               \
    asm volatile(                                                            \
        "{\n\t.reg .pred P1;\n\t"                                            \
        "WAIT_LOOP_%=:\n\t"                                                  \
        "mbarrier.try_wait.parity.acquire.cta.shared::cta.b64 P1, [%0], %1, 0x989680;\n\t" \
        "@P1 bra.uni WAIT_DONE_%=;\n\t"                                      \
        "bra.uni WAIT_LOOP_%=;\n\t"                                          \
        "WAIT_DONE_%=:\n\t}"                                                 \
        :: "r"(a), "r"(par) : "memory");                                     \
} while (0)

#define MBAR_EXPECT_TX(a, bytes) \
    asm volatile("mbarrier.arrive.expect_tx.shared.b64 _, [%0], %1;" \
                 :: "r"(a), "r"(bytes) : "memory")

#define BULK_G2S(dst, src, sz, mbar) \
    asm volatile("cp.async.bulk.shared::cta.global.mbarrier::complete_tx::bytes " \
                 "[%0], [%1], %2, [%3];" \
                 :: "r"(dst), "l"(src), "r"(sz), "r"(mbar) : "memory")

#define TC_ALLOC(smem_addr, ncols) \
    asm volatile("tcgen05.alloc.cta_group::1.sync.aligned.shared::cta.b32 [%0], %1;" \
                 :: "r"(smem_addr), "r"(ncols) : "memory")
#define TC_DEALLOC(tmem, ncols) \
    asm volatile("tcgen05.dealloc.cta_group::1.sync.aligned.b32 %0, %1;" :: "r"(tmem), "r"(ncols))
#define TC_RELINQ() \
    asm volatile("tcgen05.relinquish_alloc_permit.cta_group::1.sync.aligned;")
#define TC_COMMIT(mbar) \
    asm volatile("tcgen05.commit.cta_group::1.mbarrier::arrive::one.shared::cluster.b64 [%0];" \
                 :: "r"(mbar) : "memory")
#define TC_FENCE_AFTER()  asm volatile("tcgen05.fence::after_thread_sync;" ::: "memory")
#define TC_FENCE_BEFORE() asm volatile("tcgen05.fence::before_thread_sync;" ::: "memory")
#define TC_WAIT_LD()      asm volatile("tcgen05.wait::ld.sync.aligned;" ::: "memory")

static __device__ __forceinline__ void mma_f16_ss(
    uint32_t d_tmem, uint64_t a_desc, uint64_t b_desc, uint32_t idesc, bool acc)
{
    uint32_t en = acc ? 1u : 0u;
    asm volatile(
        "{\n\t.reg .pred p;\n\t"
        "setp.ne.u32 p, %4, 0;\n\t"
        "tcgen05.mma.cta_group::1.kind::f16 [%0], %1, %2, %3, {%5, %5, %5, %5}, p;\n\t"
        "}"
        :: "r"(d_tmem), "l"(a_desc), "l"(b_desc), "r"(idesc), "r"(en), "r"(0u)
        : "memory");
}

#define DESC_BASE ((2ULL << 61) | (1ULL << 46) | (64ULL << 32) | (1ULL << 16))
static __device__ __forceinline__ uint64_t mk_desc(uint32_t addr) {
    return DESC_BASE | ((uint64_t)(addr >> 4) & 0x3FFF);
}

#define LDTM_X32(r, a)                                                        \
    asm volatile("tcgen05.ld.sync.aligned.32x32b.x32.b32 "                    \
        "{%0,%1,%2,%3,%4,%5,%6,%7,%8,%9,%10,%11,%12,%13,%14,%15,"             \
        "%16,%17,%18,%19,%20,%21,%22,%23,%24,%25,%26,%27,%28,%29,%30,%31}, [%32];" \
        : "=r"((r)[0]),"=r"((r)[1]),"=r"((r)[2]),"=r"((r)[3]),                \
          "=r"((r)[4]),"=r"((r)[5]),"=r"((r)[6]),"=r"((r)[7]),                \
          "=r"((r)[8]),"=r"((r)[9]),"=r"((r)[10]),"=r"((r)[11]),              \
          "=r"((r)[12]),"=r"((r)[13]),"=r"((r)[14]),"=r"((r)[15]),            \
          "=r"((r)[16]),"=r"((r)[17]),"=r"((r)[18]),"=r"((r)[19]),            \
          "=r"((r)[20]),"=r"((r)[21]),"=r"((r)[22]),"=r"((r)[23]),            \
          "=r"((r)[24]),"=r"((r)[25]),"=r"((r)[26]),"=r"((r)[27]),            \
          "=r"((r)[28]),"=r"((r)[29]),"=r"((r)[30]),"=r"((r)[31])             \
        : "r"(a))
#endif // HAS_TC

// ---------------------------------------------------------------------------
// K0: transpose z (b,c,h,w) -> zflat[row][c] + bf16 3-split into tiled layout
// ---------------------------------------------------------------------------
__global__ void k_transpose(const float* __restrict__ z) {
    __shared__ float t[32][33];
    int b = blockIdx.z, h = blockIdx.y, c0 = blockIdx.x * 32;
    int tx = threadIdx.x, ty = threadIdx.y;
    t[ty][tx] = z[((size_t)(b * 256 + c0 + ty) * 32 + h) * 32 + tx];
    __syncthreads();
    int n = b * 1024 + h * 32 + ty;
    int c = c0 + tx;
    float x = t[tx][ty];
    g_zflat[(size_t)n * DIM + c] = x;
    __nv_bfloat16 h1 = __float2bfloat16(x);
    float r1 = __fsub_rn(x, __bfloat162float(h1));
    __nv_bfloat16 h2 = __float2bfloat16(r1);
    float r2 = __fsub_rn(r1, __bfloat162float(h2));
    size_t o = tiled_off(n, c);
    g_zs0[o] = h1; g_zs1[o] = h2; g_zs2[o] = __float2bfloat16(r2);
}

// ---------------------------------------------------------------------------
// K1: row norms (reference elementwise square + k-ascending sum rounding)
// ---------------------------------------------------------------------------
__global__ void k_norms(const float* __restrict__ emb) {
    int i = blockIdx.x * blockDim.x + threadIdx.x;
    if (i < NROWS) {
        const float4* p = reinterpret_cast<const float4*>(g_zflat + (size_t)i * DIM);
        float s = 0.f;
        #pragma unroll 8
        for (int c = 0; c < DIM / 4; ++c) {
            float4 v = p[c];
            s = __fadd_rn(s, __fmul_rn(v.x, v.x));
            s = __fadd_rn(s, __fmul_rn(v.y, v.y));
            s = __fadd_rn(s, __fmul_rn(v.z, v.z));
            s = __fadd_rn(s, __fmul_rn(v.w, v.w));
        }
        g_znorm[i] = s;
    } else if (i < NROWS + NCODES) {
        int k = i - NROWS;
        const float4* p = reinterpret_cast<const float4*>(emb + (size_t)k * DIM);
        float s = 0.f;
        #pragma unroll 8
        for (int c = 0; c < DIM / 4; ++c) {
            float4 v = p[c];
            s = __fadd_rn(s, __fmul_rn(v.x, v.x));
            s = __fadd_rn(s, __fmul_rn(v.y, v.y));
            s = __fadd_rn(s, __fmul_rn(v.z, v.z));
            s = __fadd_rn(s, __fmul_rn(v.w, v.w));
        }
        g_enorm[k] = s;
    }
}

// ---------------------------------------------------------------------------
// K2: embedding bf16 3-way split, vectorized 8 elements/thread.
// ---------------------------------------------------------------------------
__global__ void k_split_e(const float* __restrict__ emb) {
    int i = blockIdx.x * blockDim.x + threadIdx.x;     // i indexes groups of 8
    if (i >= NCODES * DIM / 8) return;
    int k = i >> 5, c8 = (i & 31) * 8;
    const float4* src = reinterpret_cast<const float4*>(emb + (size_t)k * DIM + c8);
    float4 v0 = src[0], v1 = src[1];
    float xs[8] = {v0.x, v0.y, v0.z, v0.w, v1.x, v1.y, v1.z, v1.w};
    __nv_bfloat16 s0[8], s1[8], s2[8];
    #pragma unroll
    for (int u = 0; u < 8; ++u) {
        float x = xs[u];
        __nv_bfloat16 h1 = __float2bfloat16(x);
        float r1 = __fsub_rn(x, __bfloat162float(h1));
        __nv_bfloat16 h2 = __float2bfloat16(r1);
        float r2 = __fsub_rn(r1, __bfloat162float(h2));
        s0[u] = h1; s1[u] = h2; s2[u] = __float2bfloat16(r2);
    }
    size_t o = tiled_off(k, c8);    // 16B-aligned, 8 elems contiguous
    *reinterpret_cast<uint4*>(g_es0 + o) = *reinterpret_cast<uint4*>(s0);
    *reinterpret_cast<uint4*>(g_es1 + o) = *reinterpret_cast<uint4*>(s1);
    *reinterpret_cast<uint4*>(g_es2 + o) = *reinterpret_cast<uint4*>(s2);
}

// ---------------------------------------------------------------------------
// K3: persistent GEMM + fused argmin. grid=148, 576 threads.
// Schedule per kc (A 2 slots X/Y = kc&1, B 3 slots):
//   j:      0      1      2      3      4      5
//   term:  z1e2   z1e3   z1e1   z2e2   z2e1   z3e1
//   aslot:  X      X      X      Y      Y      X
//   bslot:  0      1      2      0      2      2
//   load:  z1,e2   e3     e1     z2     --     z3
// Hazard distances j0:2 j1:6 j2:3 j3:4 j5:3; stage ring 8 (alias-safe d<=8).
// EPI split per subtile: sub1 workers wait EPI0 first (TMEM port drains sub0
// D cols early); consumer issues next tile's stage-0 sub0 after EPI0 and
// stage-0 sub1 after EPI1, overlapping the epilogue with tensor work.
// ---------------------------------------------------------------------------
__global__ __launch_bounds__(NTHREADS, 1) void k_mma(const float* __restrict__ emb) {
    extern __shared__ char smem[];
    const int tid = threadIdx.x;

#if HAS_TC
    const uint32_t sbase = smem_u32(smem);
    const int wid = tid >> 5;
    const int lane = tid & 31;

    if (wid == 0) TC_ALLOC(sbase + SM_TMEMPTR, 512);
    if (tid == 0) {
        #pragma unroll
        for (int q = 0; q < 8; ++q) MBAR_INIT(MB_STAGE(q) + sbase, 1);
        #pragma unroll
        for (int q = 0; q < 8; ++q) MBAR_INIT(MB_TMA(q) + sbase, 1);
        MBAR_INIT(MB_TILE(0) + sbase, 1);
        MBAR_INIT(MB_TILE(1) + sbase, 1);
        MBAR_INIT(MB_EPI0 + sbase, 256);
        MBAR_INIT(MB_EPI1 + sbase, 256);
    }
    __syncthreads();
    uint32_t tmem;
    asm volatile("ld.shared.b32 %0, [%1];" : "=r"(tmem) : "r"(sbase + SM_TMEMPTR));

    const int tab_as[6] = {0, 0, 0, 1, 1, 0};
    const int tab_bs[6] = {0, 1, 2, 0, 2, 2};
    const int tab_d[6]  = {2, 6, 3, 4, 0, 3};   // hazard distances

    if (tid == 512) {
        // ================= consumer: issue MMAs (never drains) ==============
        int ti = 0;
        for (int tile = blockIdx.x; tile < NTILES; tile += GRID_MMA, ++ti) {
            int gs = ti * STAGES_PER_TILE;
            int ln = ti * LOADS_PER_TILE;
            for (int s = 0; s < STAGES_PER_TILE; ++s, ++gs) {
                const int kc = s / 6;
                const int j  = s - kc * 6;
                if (j != 4) {
                    MBAR_WAIT(MB_TMA(ln & 7) + sbase, (ln >> 3) & 1);
                    ++ln;
                }
                const int a_slot = tab_as[j] ^ (kc & 1);
                const int b_slot = tab_bs[j];
                uint64_t bd = mk_desc(sbase + SM_B(b_slot));
                #pragma unroll
                for (int sb2 = 0; sb2 < 2; ++sb2) {
                    if (s == 0 && ti >= 1) {
                        // per-subtile D-buffer reuse guard
                        MBAR_WAIT((sb2 == 0 ? MB_EPI0 : MB_EPI1) + sbase,
                                  (ti - 1) & 1);
                        TC_FENCE_AFTER();
                    }
                    uint64_t ad = mk_desc(sbase + SM_A(a_slot) + sb2 * 16384);
                    #pragma unroll
                    for (int k = 0; k < 4; ++k)
                        mma_f16_ss(tmem + sb2 * 256, ad + k * 2, bd + k * 2,
                                   IDESC, (s > 0) || (k > 0));
                }
                TC_COMMIT(MB_STAGE(gs & 7) + sbase);
                if (s == STAGES_PER_TILE - 1)
                    TC_COMMIT(MB_TILE(ti & 1) + sbase);   // tile handoff
            }
        }
    } else if (tid == 544) {
        // ============ producer: bulk copies, per-slot hazard waits ==========
        int ti = 0;
        for (int tile = blockIdx.x; tile < NTILES; tile += GRID_MMA, ++ti) {
            const int mblk = (tile & (N_MT - 1)) * 2;   // 2 z-blocks of 128
            const int nblk = (tile / N_MT) * 2;         // 2 e-blocks of 128
            int gs = ti * STAGES_PER_TILE;
            int ln = ti * LOADS_PER_TILE;
            for (int s = 0; s < STAGES_PER_TILE; ++s, ++gs) {
                const int kc = s / 6;
                const int j  = s - kc * 6;
                if (j == 4) continue;
                const int h = gs - tab_d[j];
                if (h >= 0) MBAR_WAIT(MB_STAGE(h & 7) + sbase, (h >> 3) & 1);
                const uint32_t mb = MB_TMA(ln & 7) + sbase;
                const uint32_t bytes = (j == 0) ? 65536u : 32768u;
                MBAR_EXPECT_TX(mb, bytes);
                const int a_slot = tab_as[j] ^ (kc & 1);
                const int b_slot = tab_bs[j];
                if (j == 0 || j == 3 || j == 5) {   // A load: z1 / z2 / z3
                    const char* src = (j == 0) ? (const char*)g_zs0
                                    : (j == 3) ? (const char*)g_zs1
                                               : (const char*)g_zs2;
                    #pragma unroll
                    for (int sb2 = 0; sb2 < 2; ++sb2)
                        BULK_G2S(sbase + SM_A(a_slot) + sb2 * 16384,
                                 src + ((size_t)((mblk + sb2) * 4 + kc) << 14),
                                 16384u, mb);
                }
                if (j == 0 || j == 1 || j == 2) {   // B load: e2 / e3 / e1
                    const char* src = (j == 0) ? (const char*)g_es1
                                    : (j == 1) ? (const char*)g_es2
                                               : (const char*)g_es0;
                    #pragma unroll
                    for (int nb = 0; nb < 2; ++nb)
                        BULK_G2S(sbase + SM_B(b_slot) + nb * 16384,
                                 src + ((size_t)((nblk + nb) * 4 + kc) << 14),
                                 16384u, mb);
                }
                ++ln;
            }
        }
    } else if (wid < 16) {
        // ================= workers: epilogue =================
        const int sub  = (wid >> 2) & 1;
        const int half = wid >> 3;
        const int rl   = (wid & 3) * 32 + lane;

        int ti = 0;
        for (int tile = blockIdx.x; tile < NTILES; tile += GRID_MMA, ++ti) {
            const int m0 = (tile & (N_MT - 1)) * MT;
            const int n_tile = tile / N_MT;
            const int n0 = n_tile * NT;
            float* cd = reinterpret_cast<float*>(smem + SM_CD) + (ti & 1) * 512;
            int*   ci = reinterpret_cast<int*>(smem + SM_CI) + (ti & 1) * 512;

            MBAR_WAIT(MB_TILE(ti & 1) + sbase, (ti >> 1) & 1);
            TC_FENCE_AFTER();
            if (sub == 1) {
                // let sub0 drain the TMEM port (and free its D cols) first
                MBAR_WAIT(MB_EPI0 + sbase, ti & 1);
            }

            const float zn = g_znorm[m0 + sub * 128 + rl];
            float bd2 = 3.4e38f;
            int   bi2 = 0;
            #pragma unroll
            for (int jj = 0; jj < 4; ++jj) {
                uint32_t regs[32];
                LDTM_X32(regs, tmem + sub * 256 + half * 128 + jj * 32);
                TC_WAIT_LD();
                #pragma unroll
                for (int c = 0; c < 32; ++c) {
                    int code = n0 + half * 128 + jj * 32 + c;
                    float dot = __uint_as_float(regs[c]);
                    float d = __fmaf_rn(-2.f, dot,
                                        __fadd_rn(zn, __ldg(&g_enorm[code])));
                    if (d < bd2) { bd2 = d; bi2 = code; }
                }
            }
            TC_FENCE_BEFORE();
            MBAR_ARRIVE((sub == 0 ? MB_EPI0 : MB_EPI1) + sbase);

            cd[(sub * 128 + rl) * 2 + half] = bd2;
            ci[(sub * 128 + rl) * 2 + half] = bi2;
            asm volatile("bar.sync 1, 512;" ::: "memory");

            if (tid < 256) {
                float d0 = cd[tid * 2], d1 = cd[tid * 2 + 1];
                int   i0 = ci[tid * 2], i1 = ci[tid * 2 + 1];
                if (d1 < d0) { d0 = d1; i0 = i1; }  // half0 first => first-index
                g_cand_d[n_tile * NROWS + m0 + tid] = d0;
                g_cand_i[n_tile * NROWS + m0 + tid] = i0;
            }
            // next tile uses the other cd/ci buffer; its bar.sync separates
            // this reduce from the writes two tiles later.
        }
    }

    __syncthreads();
    if (wid == 0) {
        TC_RELINQ();
        TC_DEALLOC(tmem, 512);
    }

#else  // ---------------- fallback: fp32 FFMA2 GEMM-argmin ------------------
    float (*As)[260] = reinterpret_cast<float(*)[260]>(smem);
    float (*Bs)[132] = reinterpret_cast<float(*)[132]>(smem + 33280);

    const int tx = tid & 15;
    const int ty = tid >> 4;
    const int lk = tid & 31;
    const int lm = tid >> 5;
    const bool act = tid < 512;

    for (int tile = blockIdx.x; tile < NTILES; tile += GRID_MMA) {
        const int m0 = (tile & (N_MT - 1)) * MT;
        const int n_tile = tile / N_MT;
        const int n0 = n_tile * NT;

        float zn8[8];
        float bestd[8];
        int   besti[8];
        if (act) {
            #pragma unroll
            for (int r = 0; r < 8; ++r) {
                zn8[r] = g_znorm[m0 + ty * 8 + r];
                bestd[r] = 3.4e38f; besti[r] = 0;
            }
        }

        for (int hf = 0; hf < 2; ++hf) {
            const int nb = n0 + hf * 128;
            float2 acc[8][4];
            if (act) {
                #pragma unroll
                for (int r = 0; r < 8; ++r)
                    #pragma unroll
                    for (int j = 0; j < 4; ++j) acc[r][j] = make_float2(0.f, 0.f);
            }

            for (int k0 = 0; k0 < DIM; k0 += 32) {
                __syncthreads();
                if (act) {
                    #pragma unroll
                    for (int j = 0; j < 16; ++j) {
                        int row = lm + j * 16;
                        As[lk][row] = g_zflat[(size_t)(m0 + row) * DIM + k0 + lk];
                    }
                    #pragma unroll
                    for (int j = 0; j < 8; ++j) {
                        int row = lm + j * 16;
                        Bs[lk][row] = emb[(size_t)(nb + row) * DIM + k0 + lk];
                    }
                }
                __syncthreads();
                if (act) {
                    #pragma unroll
                    for (int k = 0; k < 32; ++k) {
                        float4 a0 = *reinterpret_cast<const float4*>(&As[k][ty * 8]);
                        float4 a1 = *reinterpret_cast<const float4*>(&As[k][ty * 8 + 4]);
                        float4 b0 = *reinterpret_cast<const float4*>(&Bs[k][tx * 8]);
                        float4 b1 = *reinterpret_cast<const float4*>(&Bs[k][tx * 8 + 4]);
                        unsigned long long bp0 = pack2(b0.x, b0.y);
                        unsigned long long bp1 = pack2(b0.z, b0.w);
                        unsigned long long bp2 = pack2(b1.x, b1.y);
                        unsigned long long bp3 = pack2(b1.z, b1.w);
                        float av[8] = {a0.x, a0.y, a0.z, a0.w, a1.x, a1.y, a1.z, a1.w};
                        #pragma unroll
                        for (int r = 0; r < 8; ++r) {
                            unsigned long long ap = dup2(av[r]);
                            fma2(acc[r][0], ap, bp0);
                            fma2(acc[r][1], ap, bp1);
                            fma2(acc[r][2], ap, bp2);
                            fma2(acc[r][3], ap, bp3);
                        }
                    }
                }
            }

            if (act) {
                #pragma unroll
                for (int j = 0; j < 8; ++j) {
                    int code = nb + tx * 8 + j;
                    float en = __ldg(&g_enorm[code]);
                    #pragma unroll
                    for (int r = 0; r < 8; ++r) {
                        float dot = (j & 1) ? acc[r][j >> 1].y : acc[r][j >> 1].x;
                        float d = __fmaf_rn(-2.f, dot, __fadd_rn(zn8[r], en));
                        if (d < bestd[r]) { bestd[r] = d; besti[r] = code; }
                    }
                }
            }
        }

        if (act) {
            #pragma unroll
            for (int r = 0; r < 8; ++r) {
                float bd = bestd[r];
                int   bi = besti[r];
                #pragma unroll
                for (int off = 8; off > 0; off >>= 1) {
                    float od = __shfl_down_sync(0xffffffffu, bd, off, 16);
                    int   oi = __shfl_down_sync(0xffffffffu, bi, off, 16);
                    if (od < bd || (od == bd && oi < bi)) { bd = od; bi = oi; }
                }
                if (tx == 0) {
                    int row = m0 + ty * 8 + r;
                    g_cand_d[n_tile * NROWS + row] = bd;
                    g_cand_i[n_tile * NROWS + row] = bi;
                }
            }
        }
        __syncthreads();
    }
#endif
}

// ---------------------------------------------------------------------------
// K4: fused merge + gather + straight-through + loss partials.
// Threads 0-63 load the 64 per-chunk candidates; lexicographic (d, idx) tree
// min == first-index global argmin. Then gather/output as before.
// ---------------------------------------------------------------------------
__global__ void k_gather(const float* __restrict__ emb, float* __restrict__ out,
                         int out_size) {
    __shared__ float red[256];
    __shared__ float md[64];
    __shared__ int   mi[64];
    int n = blockIdx.x, c = threadIdx.x;
    if (c < 64) {
        md[c] = g_cand_d[c * NROWS + n];
        mi[c] = g_cand_i[c * NROWS + n];
    }
    __syncthreads();
    #pragma unroll
    for (int s = 32; s > 0; s >>= 1) {
        if (c < s) {
            float d1 = md[c + s]; int i1 = mi[c + s];
            if (d1 < md[c] || (d1 == md[c] && i1 < mi[c])) { md[c] = d1; mi[c] = i1; }
        }
        __syncthreads();
    }
    int code = mi[0];
    if (c == 0 && out_size > OFF_IDX + n) out[OFF_IDX + n] = (float)code;

    int b = n >> 10, hw = n & 1023;
    float zf = g_zflat[(size_t)n * DIM + c];
    float zq = emb[(size_t)code * DIM + c];
    float diff = __fsub_rn(zq, zf);
    float st = __fadd_rn(zf, diff);
    out[(size_t)(b * 256 + c) * 1024 + hw] = st;
    red[c] = __fmul_rn(diff, diff);
    __syncthreads();
    #pragma unroll
    for (int s = 128; s > 0; s >>= 1) {
        if (c < s) red[c] = __fadd_rn(red[c], red[c + s]);
        __syncthreads();
    }
    if (c == 0) g_losspart[n] = red[0];
}

__global__ void k_loss(float* __restrict__ out, int out_size) {
    __shared__ float red[256];
    int t = threadIdx.x;
    float s = 0.f;
    for (int i = t; i < NROWS; i += 256) s = __fadd_rn(s, g_losspart[i]);
    red[t] = s;
    __syncthreads();
    #pragma unroll
    for (int k = 128; k > 0; k >>= 1) {
        if (t < k) red[t] = __fadd_rn(red[t], red[t + k]);
        __syncthreads();
    }
    if (t == 0 && out_size > OFF_LOSS)
        out[OFF_LOSS] = 1.25f * red[0] / 2097152.0f;
}

// ---------------------------------------------------------------------------
extern "C" void kernel_launch(void* const* d_in, const int* in_sizes, int n_in,
                              void* d_out, int out_size) {
    const float* z   = (const float*)d_in[0];
    const float* emb = (const float*)d_in[1];
    if (n_in >= 2 && in_sizes[0] == NCODES * DIM && in_sizes[1] == NROWS * DIM) {
        const float* t = z; z = emb; emb = t;
    }
    float* out = (float*)d_out;

    cudaFuncSetAttribute(k_mma, cudaFuncAttributeMaxDynamicSharedMemorySize, SMEM_DYN);

    k_transpose<<<dim3(8, 32, 8), dim3(32, 32)>>>(z);
    k_norms<<<(NROWS + NCODES + 255) / 256, 256>>>(emb);
    k_split_e<<<(NCODES * DIM / 8 + 255) / 256, 256>>>(emb);
    k_mma<<<GRID_MMA, NTHREADS, SMEM_DYN>>>(emb);
    k_gather<<<NROWS, 256>>>(emb, out, out_size);
    k_loss<<<1, 256>>>(out, out_size);
}